// round 7
// baseline (speedup 1.0000x reference)
#include <cuda_runtime.h>
#include <cuda_bf16.h>
#include <cstdint>

// ---------------------------------------------------------------------------
// TransformerBlock: windowed attention, B=4 C=192 H=W=256, 16x16 windows.
//   K0 : split W_qk -> bf16 hi/lo packed planes (per-launch, tiny)
//   K1 : merged qkv, grid (9, 1024): bx 0-5 q/k (3x bf16), bx 6-8 v (tf32)
//        q/k outputs stored PRE-SPLIT as bf16 hi/lo planes
//   K2 : attention, grid (4, 1024): Q/K smem fill = pure copies of planes
//   K3 : proj, grid (3, 1024) M-tile-fastest (L2 reuse) + 2 CTA/SM
// ---------------------------------------------------------------------------

constexpr int C_     = 192;
constexpr int NTOK   = 256;
constexpr int NWIN   = 1024;
constexpr int IMG    = 256 * 256;

// q/k as bf16 hi/lo planes, [win][tok][ch]
__device__ __align__(16) __nv_bfloat16 g_qh[(size_t)NWIN * NTOK * C_];
__device__ __align__(16) __nv_bfloat16 g_ql[(size_t)NWIN * NTOK * C_];
__device__ __align__(16) __nv_bfloat16 g_kh[(size_t)NWIN * NTOK * C_];
__device__ __align__(16) __nv_bfloat16 g_kl[(size_t)NWIN * NTOK * C_];
__device__ float g_v[(size_t)NWIN * NTOK * C_];
__device__ float g_y[(size_t)NWIN * C_ * NTOK];
// pre-split qk weights: packed bf16x2 (channels 2c,2c+1), [384 rows][96 words]
__device__ uint32_t g_wqkh[384 * 96];
__device__ uint32_t g_wqkl[384 * 96];

__device__ __forceinline__ uint32_t f2tf(float x) {
    uint32_t u;
    asm("cvt.rna.tf32.f32 %0, %1;" : "=r"(u) : "f"(x));
    return u;
}
__device__ __forceinline__ void splitbf2(float x0, float x1, uint32_t& hi, uint32_t& lo) {
    __nv_bfloat16 h0 = __float2bfloat16_rn(x0);
    __nv_bfloat16 h1 = __float2bfloat16_rn(x1);
    __nv_bfloat16 l0 = __float2bfloat16_rn(x0 - __bfloat162float(h0));
    __nv_bfloat16 l1 = __float2bfloat16_rn(x1 - __bfloat162float(h1));
    hi = ((uint32_t)__bfloat16_as_ushort(h1) << 16) | __bfloat16_as_ushort(h0);
    lo = ((uint32_t)__bfloat16_as_ushort(l1) << 16) | __bfloat16_as_ushort(l0);
}
__device__ __forceinline__ void store_hl(__nv_bfloat16* dh, __nv_bfloat16* dl,
                                         size_t i, float v) {
    __nv_bfloat16 h = __float2bfloat16_rn(v);
    dh[i] = h;
    dl[i] = __float2bfloat16_rn(v - __bfloat162float(h));
}
__device__ __forceinline__ void mma8(float* d, const uint32_t* a, const uint32_t* b) {
    asm volatile(
        "mma.sync.aligned.m16n8k8.row.col.f32.tf32.tf32.f32 "
        "{%0,%1,%2,%3}, {%4,%5,%6,%7}, {%8,%9}, {%0,%1,%2,%3};\n"
        : "+f"(d[0]), "+f"(d[1]), "+f"(d[2]), "+f"(d[3])
        : "r"(a[0]), "r"(a[1]), "r"(a[2]), "r"(a[3]),
          "r"(b[0]), "r"(b[1]));
}
__device__ __forceinline__ void mma16(float* d, const uint32_t* a, const uint32_t* b) {
    asm volatile(
        "mma.sync.aligned.m16n8k16.row.col.f32.bf16.bf16.f32 "
        "{%0,%1,%2,%3}, {%4,%5,%6,%7}, {%8,%9}, {%0,%1,%2,%3};\n"
        : "+f"(d[0]), "+f"(d[1]), "+f"(d[2]), "+f"(d[3])
        : "r"(a[0]), "r"(a[1]), "r"(a[2]), "r"(a[3]),
          "r"(b[0]), "r"(b[1]));
}

// ===========================================================================
// K0: split W_qk rows [0,384) into bf16 hi/lo packed planes.
// ===========================================================================
__global__ void split_w_kernel(const float* __restrict__ qkv_w) {
    int idx = blockIdx.x * 256 + threadIdx.x;
    if (idx >= 384 * 96) return;
    int r = idx / 96, c = idx % 96;
    uint32_t h, l;
    splitbf2(qkv_w[r * C_ + 2 * c], qkv_w[r * C_ + 2 * c + 1], h, l);
    g_wqkh[idx] = h;
    g_wqkl[idx] = l;
}

// ===========================================================================
// K1: merged qkv. grid (9, 1024), 256 thr, 2 CTA/SM.
// ===========================================================================
constexpr int AS3 = 20;
constexpr int BS3 = 264;
constexpr size_t SMEM_QKV_BYTES = (size_t)(2 * 64 * AS3 + 2 * 16 * BS3) * 4;  // 44032

__global__ void __launch_bounds__(256, 2) qkv_kernel(const float* __restrict__ x,
                                                     const float* __restrict__ qkv_w,
                                                     const float* __restrict__ qkv_b) {
    extern __shared__ uint32_t smq[];

    const int w  = blockIdx.y;
    const int b  = w >> 8, wh = (w >> 4) & 15, ww = w & 15;
    const int tid = threadIdx.x, warp = tid >> 5, lane = tid & 31;
    const int wm = (warp >> 2) << 5;
    const int wn = (warp & 3) << 6;
    const float* xw = x + (size_t)b * C_ * IMG + (size_t)(wh * 16) * 256 + ww * 16;

    float acc[2][8][4];
#pragma unroll
    for (int i = 0; i < 2; i++)
#pragma unroll
        for (int j = 0; j < 8; j++)
#pragma unroll
            for (int r = 0; r < 4; r++) acc[i][j][r] = 0.f;

    if (blockIdx.x < 6) {
        // ---------------- q/k path: 3x bf16 ----------------
        uint32_t* Ah = smq;
        uint32_t* Al = Ah + 64 * AS3;
        uint32_t* Bh = Al + 64 * AS3;
        uint32_t* Bl = Bh + 16 * BS3;
        const int m0 = blockIdx.x * 64;

        for (int k0 = 0; k0 < C_; k0 += 32) {
            const int kw0 = k0 >> 1;
#pragma unroll
            for (int t = tid; t < 256; t += 256) {
                int r = t >> 2, c4 = (t & 3) << 2;
                *reinterpret_cast<uint4*>(&Ah[r * AS3 + c4]) =
                    *reinterpret_cast<const uint4*>(&g_wqkh[(m0 + r) * 96 + kw0 + c4]);
                *reinterpret_cast<uint4*>(&Al[r * AS3 + c4]) =
                    *reinterpret_cast<const uint4*>(&g_wqkl[(m0 + r) * 96 + kw0 + c4]);
            }
#pragma unroll
            for (int t = tid; t < 1024; t += 256) {
                int kp = t >> 6, q = t & 63;
                int i = q >> 2, j4 = (q & 3) << 2;
                const float* p0 = xw + (size_t)(k0 + 2 * kp) * IMG + i * 256 + j4;
                float4 v0 = *reinterpret_cast<const float4*>(p0);
                float4 v1 = *reinterpret_cast<const float4*>(p0 + IMG);
                uint32_t* dh = &Bh[kp * BS3 + i * 16 + j4];
                uint32_t* dl = &Bl[kp * BS3 + i * 16 + j4];
                uint32_t h, l;
                splitbf2(v0.x, v1.x, h, l); dh[0] = h; dl[0] = l;
                splitbf2(v0.y, v1.y, h, l); dh[1] = h; dl[1] = l;
                splitbf2(v0.z, v1.z, h, l); dh[2] = h; dl[2] = l;
                splitbf2(v0.w, v1.w, h, l); dh[3] = h; dl[3] = l;
            }
            __syncthreads();

#pragma unroll
            for (int kk2 = 0; kk2 < 16; kk2 += 8) {
                uint32_t ah[2][4], al[2][4];
#pragma unroll
                for (int im = 0; im < 2; im++) {
                    int r  = wm + im * 16 + (lane >> 2);
                    int cc = kk2 + (lane & 3);
                    ah[im][0] = Ah[r * AS3 + cc];           al[im][0] = Al[r * AS3 + cc];
                    ah[im][1] = Ah[(r + 8) * AS3 + cc];     al[im][1] = Al[(r + 8) * AS3 + cc];
                    ah[im][2] = Ah[r * AS3 + cc + 4];       al[im][2] = Al[r * AS3 + cc + 4];
                    ah[im][3] = Ah[(r + 8) * AS3 + cc + 4]; al[im][3] = Al[(r + 8) * AS3 + cc + 4];
                }
#pragma unroll
                for (int in = 0; in < 8; in++) {
                    int col = wn + in * 8 + (lane >> 2);
                    uint32_t bh[2], bl[2];
                    bh[0] = Bh[(kk2 + (lane & 3)) * BS3 + col];
                    bl[0] = Bl[(kk2 + (lane & 3)) * BS3 + col];
                    bh[1] = Bh[(kk2 + 4 + (lane & 3)) * BS3 + col];
                    bl[1] = Bl[(kk2 + 4 + (lane & 3)) * BS3 + col];
#pragma unroll
                    for (int im = 0; im < 2; im++) {
                        mma16(acc[im][in], ah[im], bl);
                        mma16(acc[im][in], al[im], bh);
                        mma16(acc[im][in], ah[im], bh);
                    }
                }
            }
            __syncthreads();
        }

        const int sec = m0 / 192;
        const int ob  = m0 % 192;
        __nv_bfloat16* dh = (sec == 0) ? g_qh : g_kh;
        __nv_bfloat16* dl = (sec == 0) ? g_ql : g_kl;
        const size_t base = (size_t)w * NTOK * C_;
#pragma unroll
        for (int im = 0; im < 2; im++) {
            int mr = wm + im * 16 + (lane >> 2);
            float b0 = qkv_b[m0 + mr];
            float b1 = qkv_b[m0 + mr + 8];
#pragma unroll
            for (int in = 0; in < 8; in++) {
                int n0 = wn + in * 8 + ((lane & 3) << 1);
                store_hl(dh, dl, base + (size_t)n0 * C_ + ob + mr,           acc[im][in][0] + b0);
                store_hl(dh, dl, base + (size_t)(n0 + 1) * C_ + ob + mr,     acc[im][in][1] + b0);
                store_hl(dh, dl, base + (size_t)n0 * C_ + ob + mr + 8,       acc[im][in][2] + b1);
                store_hl(dh, dl, base + (size_t)(n0 + 1) * C_ + ob + mr + 8, acc[im][in][3] + b1);
            }
        }
    } else {
        // ---------------- v path: 1x tf32 ----------------
        uint32_t* As = smq;
        uint32_t* Bs = As + 64 * 36;
        const int m0 = 384 + (blockIdx.x - 6) * 64;

        for (int k0 = 0; k0 < C_; k0 += 32) {
#pragma unroll
            for (int t = tid; t < 512; t += 256) {
                int r = t >> 3, c4 = (t & 7) << 2;
                float4 v = *reinterpret_cast<const float4*>(&qkv_w[(m0 + r) * C_ + k0 + c4]);
                uint4 h;
                h.x = f2tf(v.x); h.y = f2tf(v.y); h.z = f2tf(v.z); h.w = f2tf(v.w);
                *reinterpret_cast<uint4*>(&As[r * 36 + c4]) = h;
            }
#pragma unroll
            for (int t = tid; t < 2048; t += 256) {
                int c = t >> 6, q = t & 63;
                int i = q >> 2, j4 = (q & 3) << 2;
                float4 v = *reinterpret_cast<const float4*>(xw + (size_t)(k0 + c) * IMG + i * 256 + j4);
                uint4 h;
                h.x = f2tf(v.x); h.y = f2tf(v.y); h.z = f2tf(v.z); h.w = f2tf(v.w);
                *reinterpret_cast<uint4*>(&Bs[c * 264 + i * 16 + j4]) = h;
            }
            __syncthreads();

            for (int kk = 0; kk < 32; kk += 8) {
                uint32_t a[2][4];
#pragma unroll
                for (int im = 0; im < 2; im++) {
                    int r  = wm + im * 16 + (lane >> 2);
                    int cc = kk + (lane & 3);
                    a[im][0] = As[r * 36 + cc];
                    a[im][1] = As[(r + 8) * 36 + cc];
                    a[im][2] = As[r * 36 + cc + 4];
                    a[im][3] = As[(r + 8) * 36 + cc + 4];
                }
#pragma unroll
                for (int in = 0; in < 8; in++) {
                    int col = wn + in * 8 + (lane >> 2);
                    uint32_t bf[2];
                    bf[0] = Bs[(kk + (lane & 3)) * 264 + col];
                    bf[1] = Bs[(kk + 4 + (lane & 3)) * 264 + col];
#pragma unroll
                    for (int im = 0; im < 2; im++) mma8(acc[im][in], a[im], bf);
                }
            }
            __syncthreads();
        }

        const int ob = m0 - 384;
        const size_t base = (size_t)w * NTOK * C_;
#pragma unroll
        for (int im = 0; im < 2; im++) {
            int mr = wm + im * 16 + (lane >> 2);
            float b0 = qkv_b[m0 + mr];
            float b1 = qkv_b[m0 + mr + 8];
#pragma unroll
            for (int in = 0; in < 8; in++) {
                int n0 = wn + in * 8 + ((lane & 3) << 1);
                g_v[base + (size_t)n0 * C_ + ob + mr]            = acc[im][in][0] + b0;
                g_v[base + (size_t)(n0 + 1) * C_ + ob + mr]      = acc[im][in][1] + b0;
                g_v[base + (size_t)n0 * C_ + ob + mr + 8]        = acc[im][in][2] + b1;
                g_v[base + (size_t)(n0 + 1) * C_ + ob + mr + 8]  = acc[im][in][3] + b1;
            }
        }
    }
}

// ===========================================================================
// K2: attention. grid (4, 1024), 512 thr. Q/K smem fill = plane copies.
// smem words: Qh/Ql [64][100]=6400 ea, Kh/Kl [128][100]=12800 ea,
//             S [64][260]=16640  -> 220160 B. V reuses K region (tf32, 196).
// ===========================================================================
constexpr int QS2 = 100;
constexpr int VSS = 196;
constexpr int SSS = 260;
constexpr size_t SMEM_ATTN_BYTES = (size_t)(2 * 6400 + 2 * 12800 + 16640) * 4;  // 220160

__global__ void __launch_bounds__(512, 1) attn_kernel() {
    extern __shared__ uint32_t sm[];
    uint32_t* Qh  = sm;
    uint32_t* Ql  = sm + 6400;
    uint32_t* Kh  = sm + 12800;
    uint32_t* Kl  = Kh + 12800;
    uint32_t* Ssm = sm + 12800 + 25600;

    const int qb = blockIdx.x, w = blockIdx.y;
    const int tid = threadIdx.x, warp = tid >> 5, lane = tid & 31;
    const size_t wbase = (size_t)w * NTOK * C_;

    // Q: copy 64 rows x 96 words from planes (uint4 = 8 bf16 = 4 words)
    const size_t qoff = wbase + (size_t)qb * 64 * C_;
#pragma unroll
    for (int t = tid; t < 64 * 24; t += 512) {
        int r = t / 24, g = (t % 24) << 2;      // word index
        *reinterpret_cast<uint4*>(&Qh[r * QS2 + g]) =
            *reinterpret_cast<const uint4*>(g_qh + qoff + (size_t)r * C_ + (g << 1));
        *reinterpret_cast<uint4*>(&Ql[r * QS2 + g]) =
            *reinterpret_cast<const uint4*>(g_ql + qoff + (size_t)r * C_ + (g << 1));
    }

    const int wm = (warp >> 3) << 5;
    const int wk = (warp & 7) << 4;

    // ---- S = Q K^T (3x bf16): two 128-key chunks ----
    for (int cb = 0; cb < 2; cb++) {
        const size_t koff = wbase + (size_t)cb * 128 * C_;
#pragma unroll
        for (int t = tid; t < 128 * 24; t += 512) {
            int r = t / 24, g = (t % 24) << 2;
            *reinterpret_cast<uint4*>(&Kh[r * QS2 + g]) =
                *reinterpret_cast<const uint4*>(g_kh + koff + (size_t)r * C_ + (g << 1));
            *reinterpret_cast<uint4*>(&Kl[r * QS2 + g]) =
                *reinterpret_cast<const uint4*>(g_kl + koff + (size_t)r * C_ + (g << 1));
        }
        __syncthreads();

        float sacc[2][2][4];
#pragma unroll
        for (int i = 0; i < 2; i++)
#pragma unroll
            for (int j = 0; j < 2; j++)
#pragma unroll
                for (int r = 0; r < 4; r++) sacc[i][j][r] = 0.f;

#pragma unroll
        for (int kk2 = 0; kk2 < 96; kk2 += 8) {
            uint32_t ah[2][4], al[2][4];
#pragma unroll
            for (int im = 0; im < 2; im++) {
                int r  = wm + im * 16 + (lane >> 2);
                int cc = kk2 + (lane & 3);
                ah[im][0] = Qh[r * QS2 + cc];           al[im][0] = Ql[r * QS2 + cc];
                ah[im][1] = Qh[(r + 8) * QS2 + cc];     al[im][1] = Ql[(r + 8) * QS2 + cc];
                ah[im][2] = Qh[r * QS2 + cc + 4];       al[im][2] = Ql[r * QS2 + cc + 4];
                ah[im][3] = Qh[(r + 8) * QS2 + cc + 4]; al[im][3] = Ql[(r + 8) * QS2 + cc + 4];
            }
#pragma unroll
            for (int in = 0; in < 2; in++) {
                int key = wk + in * 8 + (lane >> 2);
                uint32_t bh[2], bl[2];
                bh[0] = Kh[key * QS2 + kk2 + (lane & 3)];
                bl[0] = Kl[key * QS2 + kk2 + (lane & 3)];
                bh[1] = Kh[key * QS2 + kk2 + 4 + (lane & 3)];
                bl[1] = Kl[key * QS2 + kk2 + 4 + (lane & 3)];
#pragma unroll
                for (int im = 0; im < 2; im++) {
                    mma16(sacc[im][in], ah[im], bl);
                    mma16(sacc[im][in], al[im], bh);
                    mma16(sacc[im][in], ah[im], bh);
                }
            }
        }
#pragma unroll
        for (int im = 0; im < 2; im++) {
            int r0 = wm + im * 16 + (lane >> 2);
#pragma unroll
            for (int in = 0; in < 2; in++) {
                int c0 = cb * 128 + wk + in * 8 + ((lane & 3) << 1);
                Ssm[r0 * SSS + c0]           = __float_as_uint(sacc[im][in][0]);
                Ssm[r0 * SSS + c0 + 1]       = __float_as_uint(sacc[im][in][1]);
                Ssm[(r0 + 8) * SSS + c0]     = __float_as_uint(sacc[im][in][2]);
                Ssm[(r0 + 8) * SSS + c0 + 1] = __float_as_uint(sacc[im][in][3]);
            }
        }
        __syncthreads();
    }

    // ---- softmax (16 warps x 4 rows of 256); P stored as tf32 ----
#pragma unroll
    for (int rr = 0; rr < 4; rr++) {
        int row = warp * 4 + rr;
        float v[8];
        float mx = -3.0e38f;
#pragma unroll
        for (int i = 0; i < 8; i++) {
            v[i] = __uint_as_float(Ssm[row * SSS + lane + (i << 5)]);
            mx = fmaxf(mx, v[i]);
        }
#pragma unroll
        for (int off = 16; off; off >>= 1) mx = fmaxf(mx, __shfl_xor_sync(0xffffffffu, mx, off));
        float sum = 0.f;
#pragma unroll
        for (int i = 0; i < 8; i++) { v[i] = __expf(v[i] - mx); sum += v[i]; }
#pragma unroll
        for (int off = 16; off; off >>= 1) sum += __shfl_xor_sync(0xffffffffu, sum, off);
        float inv = 1.0f / sum;
#pragma unroll
        for (int i = 0; i < 8; i++) Ssm[row * SSS + lane + (i << 5)] = f2tf(v[i] * inv);
    }
    __syncthreads();

    // ---- O = P @ V (1x tf32): two 128-token chunks; V in Kh region ----
    const int wc = (warp & 7) * 24;
    float oacc[2][3][4];
#pragma unroll
    for (int i = 0; i < 2; i++)
#pragma unroll
        for (int j = 0; j < 3; j++)
#pragma unroll
            for (int r = 0; r < 4; r++) oacc[i][j][r] = 0.f;

    for (int vb = 0; vb < 2; vb++) {
        const float* vsrc = g_v + wbase + (size_t)vb * 128 * C_;
#pragma unroll
        for (int t = tid; t < 128 * 48; t += 512) {
            int r = t / 48, c4 = (t % 48) << 2;
            float4 v = *reinterpret_cast<const float4*>(vsrc + r * C_ + c4);
            uint32_t* d = &Kh[r * VSS + c4];
            d[0] = f2tf(v.x); d[1] = f2tf(v.y); d[2] = f2tf(v.z); d[3] = f2tf(v.w);
        }
        __syncthreads();

#pragma unroll
        for (int kk = 0; kk < 128; kk += 8) {
            uint32_t a[2][4];
#pragma unroll
            for (int im = 0; im < 2; im++) {
                int r  = wm + im * 16 + (lane >> 2);
                int cc = vb * 128 + kk + (lane & 3);
                a[im][0] = Ssm[r * SSS + cc];
                a[im][1] = Ssm[(r + 8) * SSS + cc];
                a[im][2] = Ssm[r * SSS + cc + 4];
                a[im][3] = Ssm[(r + 8) * SSS + cc + 4];
            }
#pragma unroll
            for (int in = 0; in < 3; in++) {
                int col = wc + in * 8 + (lane >> 2);
                uint32_t bf[2];
                bf[0] = Kh[(kk + (lane & 3)) * VSS + col];
                bf[1] = Kh[(kk + 4 + (lane & 3)) * VSS + col];
#pragma unroll
                for (int im = 0; im < 2; im++) mma8(oacc[im][in], a[im], bf);
            }
        }
        __syncthreads();
    }

    const size_t ybase = (size_t)w * C_ * NTOK;
#pragma unroll
    for (int im = 0; im < 2; im++) {
        int q0 = qb * 64 + wm + im * 16 + (lane >> 2);
#pragma unroll
        for (int in = 0; in < 3; in++) {
            int c0 = wc + in * 8 + ((lane & 3) << 1);
            g_y[ybase + (size_t)c0 * NTOK + q0]           = oacc[im][in][0];
            g_y[ybase + (size_t)(c0 + 1) * NTOK + q0]     = oacc[im][in][1];
            g_y[ybase + (size_t)c0 * NTOK + q0 + 8]       = oacc[im][in][2];
            g_y[ybase + (size_t)(c0 + 1) * NTOK + q0 + 8] = oacc[im][in][3];
        }
    }
}

// ===========================================================================
// K3: proj + bias + residual (1x tf32). grid (3, 1024) M-tile fastest,
// 256 thr, 2 CTA/SM. y re-reads served from L2.
// ===========================================================================
constexpr size_t SMEM_PROJ_BYTES = (size_t)(64 * 36 + 32 * 264) * 4;  // 43008

__global__ void __launch_bounds__(256, 2) proj_kernel(const float* __restrict__ x,
                                                      const float* __restrict__ proj_w,
                                                      const float* __restrict__ proj_b,
                                                      float* __restrict__ out) {
    extern __shared__ uint32_t smp[];
    uint32_t* As = smp;
    uint32_t* Bs = smp + 64 * 36;

    const int m0 = blockIdx.x * 64;
    const int w  = blockIdx.y;
    const int b  = w >> 8, wh = (w >> 4) & 15, ww = w & 15;
    const int tid = threadIdx.x, warp = tid >> 5, lane = tid & 31;
    const int wm = (warp >> 2) << 5, wn = (warp & 3) << 6;

    float acc[2][8][4];
#pragma unroll
    for (int i = 0; i < 2; i++)
#pragma unroll
        for (int j = 0; j < 8; j++)
#pragma unroll
            for (int r = 0; r < 4; r++) acc[i][j][r] = 0.f;

    const float* ysrc = g_y + (size_t)w * C_ * NTOK;

    for (int k0 = 0; k0 < C_; k0 += 32) {
#pragma unroll
        for (int t = tid; t < 512; t += 256) {
            int r = t >> 3, c4 = (t & 7) << 2;
            float4 v = *reinterpret_cast<const float4*>(&proj_w[(m0 + r) * C_ + k0 + c4]);
            uint4 h;
            h.x = f2tf(v.x); h.y = f2tf(v.y); h.z = f2tf(v.z); h.w = f2tf(v.w);
            *reinterpret_cast<uint4*>(&As[r * 36 + c4]) = h;
        }
#pragma unroll
        for (int t = tid; t < 2048; t += 256) {
            int c = t >> 6, n4 = (t & 63) << 2;
            float4 v = *reinterpret_cast<const float4*>(ysrc + (size_t)(k0 + c) * NTOK + n4);
            uint4 h;
            h.x = f2tf(v.x); h.y = f2tf(v.y); h.z = f2tf(v.z); h.w = f2tf(v.w);
            *reinterpret_cast<uint4*>(&Bs[c * 264 + n4]) = h;
        }
        __syncthreads();

#pragma unroll
        for (int kk = 0; kk < 32; kk += 8) {
            uint32_t a[2][4];
#pragma unroll
            for (int im = 0; im < 2; im++) {
                int r  = wm + im * 16 + (lane >> 2);
                int cc = kk + (lane & 3);
                a[im][0] = As[r * 36 + cc];
                a[im][1] = As[(r + 8) * 36 + cc];
                a[im][2] = As[r * 36 + cc + 4];
                a[im][3] = As[(r + 8) * 36 + cc + 4];
            }
#pragma unroll
            for (int in = 0; in < 8; in++) {
                int col = wn + in * 8 + (lane >> 2);
                uint32_t bf[2];
                bf[0] = Bs[(kk + (lane & 3)) * 264 + col];
                bf[1] = Bs[(kk + 4 + (lane & 3)) * 264 + col];
#pragma unroll
                for (int im = 0; im < 2; im++) mma8(acc[im][in], a[im], bf);
            }
        }
        __syncthreads();
    }

    // direct epilogue: float2 stores, +bias +residual
#pragma unroll
    for (int im = 0; im < 2; im++) {
        int mr = wm + im * 16 + (lane >> 2);
        int ch = m0 + mr;
        float b0 = proj_b[ch];
        float b1 = proj_b[ch + 8];
#pragma unroll
        for (int in = 0; in < 8; in++) {
            int n0 = wn + in * 8 + ((lane & 3) << 1);
            int i = n0 >> 4, j = n0 & 15;
            size_t g0 = (((size_t)b * C_ + ch) * 256 + wh * 16 + i) * 256 + ww * 16 + j;
            size_t g1 = (((size_t)b * C_ + ch + 8) * 256 + wh * 16 + i) * 256 + ww * 16 + j;
            float2 x0 = *reinterpret_cast<const float2*>(&x[g0]);
            float2 x1 = *reinterpret_cast<const float2*>(&x[g1]);
            float2 r0, r1;
            r0.x = acc[im][in][0] + b0 + x0.x;
            r0.y = acc[im][in][1] + b0 + x0.y;
            r1.x = acc[im][in][2] + b1 + x1.x;
            r1.y = acc[im][in][3] + b1 + x1.y;
            *reinterpret_cast<float2*>(&out[g0]) = r0;
            *reinterpret_cast<float2*>(&out[g1]) = r1;
        }
    }
}

// ---------------------------------------------------------------------------
namespace {
struct WarmUp {
    WarmUp() {
        void* p = nullptr;
        cudaGetSymbolAddress(&p, g_qh);
        cudaGetSymbolAddress(&p, g_ql);
        cudaGetSymbolAddress(&p, g_kh);
        cudaGetSymbolAddress(&p, g_kl);
        cudaGetSymbolAddress(&p, g_v);
        cudaGetSymbolAddress(&p, g_y);
        cudaGetSymbolAddress(&p, g_wqkh);
        cudaGetSymbolAddress(&p, g_wqkl);
        cudaFuncSetAttribute(attn_kernel, cudaFuncAttributeMaxDynamicSharedMemorySize,
                             (int)SMEM_ATTN_BYTES);
        cudaFuncSetAttribute(qkv_kernel, cudaFuncAttributeMaxDynamicSharedMemorySize,
                             (int)SMEM_QKV_BYTES);
        cudaFuncSetAttribute(proj_kernel, cudaFuncAttributeMaxDynamicSharedMemorySize,
                             (int)SMEM_PROJ_BYTES);
    }
};
WarmUp warm_;
}  // namespace

extern "C" void kernel_launch(void* const* d_in, const int* in_sizes, int n_in,
                              void* d_out, int out_size) {
    (void)in_sizes; (void)n_in; (void)out_size;
    const float* x      = (const float*)d_in[0];
    const float* qkv_w  = (const float*)d_in[1];
    const float* qkv_b  = (const float*)d_in[2];
    const float* proj_w = (const float*)d_in[3];
    const float* proj_b = (const float*)d_in[4];
    float* out = (float*)d_out;

    cudaFuncSetAttribute(attn_kernel, cudaFuncAttributeMaxDynamicSharedMemorySize,
                         (int)SMEM_ATTN_BYTES);
    cudaFuncSetAttribute(qkv_kernel, cudaFuncAttributeMaxDynamicSharedMemorySize,
                         (int)SMEM_QKV_BYTES);
    cudaFuncSetAttribute(proj_kernel, cudaFuncAttributeMaxDynamicSharedMemorySize,
                         (int)SMEM_PROJ_BYTES);

    split_w_kernel<<<144, 256>>>(qkv_w);
    qkv_kernel<<<dim3(9, NWIN), 256, SMEM_QKV_BYTES>>>(x, qkv_w, qkv_b);
    attn_kernel<<<dim3(4, NWIN), 512, SMEM_ATTN_BYTES>>>();
    proj_kernel<<<dim3(3, NWIN), 256, SMEM_PROJ_BYTES>>>(x, proj_w, proj_b, out);
}

// round 8
// speedup vs baseline: 1.0888x; 1.0888x over previous
#include <cuda_runtime.h>
#include <cuda_bf16.h>
#include <cstdint>

// ---------------------------------------------------------------------------
// TransformerBlock: windowed attention, B=4 C=192 H=W=256, 16x16 windows.
//   K0 : split W_qk -> bf16 hi/lo packed planes
//   K1 : merged qkv, grid (9, 1024): bx 0-5 q/k (3x bf16), bx 6-8 v (tf32)
//   K2 : attention, grid (4, 1024), 512 thr
//   K3 : proj, grid (3, 1024), 256 thr, 2 CTA/SM
// All mma fragment loads via ldmatrix where layout permits (L1TEX was the wall).
// ---------------------------------------------------------------------------

constexpr int C_     = 192;
constexpr int NTOK   = 256;
constexpr int NWIN   = 1024;
constexpr int IMG    = 256 * 256;

__device__ float g_q[(size_t)NWIN * NTOK * C_];
__device__ float g_k[(size_t)NWIN * NTOK * C_];
__device__ float g_v[(size_t)NWIN * NTOK * C_];
__device__ float g_y[(size_t)NWIN * C_ * NTOK];
// pre-split qk weights: packed bf16x2 (channels 2c,2c+1), [384 rows][96 words]
__device__ uint32_t g_wqkh[384 * 96];
__device__ uint32_t g_wqkl[384 * 96];

__device__ __forceinline__ uint32_t f2tf(float x) {
    uint32_t u;
    asm("cvt.rna.tf32.f32 %0, %1;" : "=r"(u) : "f"(x));
    return u;
}
__device__ __forceinline__ void splitbf2(float x0, float x1, uint32_t& hi, uint32_t& lo) {
    __nv_bfloat16 h0 = __float2bfloat16_rn(x0);
    __nv_bfloat16 h1 = __float2bfloat16_rn(x1);
    __nv_bfloat16 l0 = __float2bfloat16_rn(x0 - __bfloat162float(h0));
    __nv_bfloat16 l1 = __float2bfloat16_rn(x1 - __bfloat162float(h1));
    hi = ((uint32_t)__bfloat16_as_ushort(h1) << 16) | __bfloat16_as_ushort(h0);
    lo = ((uint32_t)__bfloat16_as_ushort(l1) << 16) | __bfloat16_as_ushort(l0);
}
__device__ __forceinline__ uint32_t sptr(const void* p) {
    return (uint32_t)__cvta_generic_to_shared(p);
}
__device__ __forceinline__ void ldsm4(uint32_t* r, uint32_t a) {
    asm volatile("ldmatrix.sync.aligned.m8n8.x4.shared.b16 {%0,%1,%2,%3}, [%4];"
        : "=r"(r[0]), "=r"(r[1]), "=r"(r[2]), "=r"(r[3]) : "r"(a));
}
__device__ __forceinline__ void ldsm4t(uint32_t* r, uint32_t a) {
    asm volatile("ldmatrix.sync.aligned.m8n8.x4.trans.shared.b16 {%0,%1,%2,%3}, [%4];"
        : "=r"(r[0]), "=r"(r[1]), "=r"(r[2]), "=r"(r[3]) : "r"(a));
}
__device__ __forceinline__ void mma8(float* d, const uint32_t* a, const uint32_t* b) {
    asm volatile(
        "mma.sync.aligned.m16n8k8.row.col.f32.tf32.tf32.f32 "
        "{%0,%1,%2,%3}, {%4,%5,%6,%7}, {%8,%9}, {%0,%1,%2,%3};\n"
        : "+f"(d[0]), "+f"(d[1]), "+f"(d[2]), "+f"(d[3])
        : "r"(a[0]), "r"(a[1]), "r"(a[2]), "r"(a[3]),
          "r"(b[0]), "r"(b[1]));
}
__device__ __forceinline__ void mma16(float* d, const uint32_t* a, const uint32_t* b) {
    asm volatile(
        "mma.sync.aligned.m16n8k16.row.col.f32.bf16.bf16.f32 "
        "{%0,%1,%2,%3}, {%4,%5,%6,%7}, {%8,%9}, {%0,%1,%2,%3};\n"
        : "+f"(d[0]), "+f"(d[1]), "+f"(d[2]), "+f"(d[3])
        : "r"(a[0]), "r"(a[1]), "r"(a[2]), "r"(a[3]),
          "r"(b[0]), "r"(b[1]));
}

// ===========================================================================
// K0: split W_qk rows [0,384) into bf16 hi/lo packed planes.
// ===========================================================================
__global__ void split_w_kernel(const float* __restrict__ qkv_w) {
    int idx = blockIdx.x * 256 + threadIdx.x;
    if (idx >= 384 * 96) return;
    int r = idx / 96, c = idx % 96;
    uint32_t h, l;
    splitbf2(qkv_w[r * C_ + 2 * c], qkv_w[r * C_ + 2 * c + 1], h, l);
    g_wqkh[idx] = h;
    g_wqkl[idx] = l;
}

// ===========================================================================
// K1: merged qkv. grid (9, 1024), 256 thr, 2 CTA/SM. smem 44032 B.
// q/k path: A packed [row][kpair] (ldsm4), B unpacked bf16 [ch][tok] (ldsm4t)
// ===========================================================================
constexpr int AS3 = 20;       // A stride (words)
constexpr int BT16 = 264;     // B stride (b16 elements) = 132 words
constexpr size_t SMEM_QKV_BYTES = (size_t)(2 * 64 * AS3 + 2 * 32 * 132) * 4;  // 44032

__global__ void __launch_bounds__(256, 2) qkv_kernel(const float* __restrict__ x,
                                                     const float* __restrict__ qkv_w,
                                                     const float* __restrict__ qkv_b) {
    extern __shared__ uint32_t smq[];

    const int w  = blockIdx.y;
    const int b  = w >> 8, wh = (w >> 4) & 15, ww = w & 15;
    const int tid = threadIdx.x, warp = tid >> 5, lane = tid & 31;
    const int wm = (warp >> 2) << 5;
    const int wn = (warp & 3) << 6;
    const float* xw = x + (size_t)b * C_ * IMG + (size_t)(wh * 16) * 256 + ww * 16;

    float acc[2][8][4];
#pragma unroll
    for (int i = 0; i < 2; i++)
#pragma unroll
        for (int j = 0; j < 8; j++)
#pragma unroll
            for (int r = 0; r < 4; r++) acc[i][j][r] = 0.f;

    if (blockIdx.x < 6) {
        // ---------------- q/k path: 3x bf16 ----------------
        uint32_t* Ah = smq;                        // [64][20] words
        uint32_t* Al = Ah + 64 * AS3;
        uint16_t* Bh16 = (uint16_t*)(smq + 2 * 64 * AS3);            // [32][264] b16
        uint16_t* Bl16 = Bh16 + 32 * BT16;
        const int m0 = blockIdx.x * 64;

        const int arow = wm + (lane & 7) + ((lane & 8) ? 8 : 0);
        const int asel = (lane & 16) ? 4 : 0;
        const int brow0 = (lane & 7) + ((lane & 8) ? 8 : 0);
        const int bsel = (lane & 16) ? 8 : 0;

        for (int k0 = 0; k0 < C_; k0 += 32) {
            const int kw0 = k0 >> 1;
            // A: copy pre-split planes (64 rows x 16 words)
#pragma unroll
            for (int t = tid; t < 256; t += 256) {
                int r = t >> 2, c4 = (t & 3) << 2;
                *reinterpret_cast<uint4*>(&Ah[r * AS3 + c4]) =
                    *reinterpret_cast<const uint4*>(&g_wqkh[(m0 + r) * 96 + kw0 + c4]);
                *reinterpret_cast<uint4*>(&Al[r * AS3 + c4]) =
                    *reinterpret_cast<const uint4*>(&g_wqkl[(m0 + r) * 96 + kw0 + c4]);
            }
            // B: x window -> unpacked bf16 [ch][tok] planes
#pragma unroll
            for (int t = tid; t < 2048; t += 256) {
                int c = t >> 6, q = t & 63;
                int i = q >> 2, j4 = (q & 3) << 2;
                float4 v = *reinterpret_cast<const float4*>(
                    xw + (size_t)(k0 + c) * IMG + i * 256 + j4);
                int tok = i * 16 + j4;
                uint32_t h01, l01, h23, l23;
                splitbf2(v.x, v.y, h01, l01);   // tokens tok, tok+1 (same ch)
                splitbf2(v.z, v.w, h23, l23);
                uint32_t* dh = reinterpret_cast<uint32_t*>(&Bh16[c * BT16 + tok]);
                uint32_t* dl = reinterpret_cast<uint32_t*>(&Bl16[c * BT16 + tok]);
                dh[0] = h01; dh[1] = h23;
                dl[0] = l01; dl[1] = l23;
            }
            __syncthreads();

#pragma unroll
            for (int kk = 0; kk < 32; kk += 16) {
                uint32_t ah[2][4], al[2][4];
                int awrd = (kk >> 1) + asel;
                ldsm4(ah[0], sptr(&Ah[arow * AS3 + awrd]));
                ldsm4(ah[1], sptr(&Ah[(arow + 16) * AS3 + awrd]));
                ldsm4(al[0], sptr(&Al[arow * AS3 + awrd]));
                ldsm4(al[1], sptr(&Al[(arow + 16) * AS3 + awrd]));
                int brow = kk + brow0;
#pragma unroll
                for (int inp = 0; inp < 4; inp++) {
                    int n0 = wn + inp * 16 + bsel;
                    uint32_t bh4[4], bl4[4];
                    ldsm4t(bh4, sptr(&Bh16[brow * BT16 + n0]));
                    ldsm4t(bl4, sptr(&Bl16[brow * BT16 + n0]));
#pragma unroll
                    for (int im = 0; im < 2; im++) {
                        mma16(acc[im][2 * inp],     ah[im], bl4);
                        mma16(acc[im][2 * inp],     al[im], bh4);
                        mma16(acc[im][2 * inp],     ah[im], bh4);
                        mma16(acc[im][2 * inp + 1], ah[im], bl4 + 2);
                        mma16(acc[im][2 * inp + 1], al[im], bh4 + 2);
                        mma16(acc[im][2 * inp + 1], ah[im], bh4 + 2);
                    }
                }
            }
            __syncthreads();
        }

        const int sec = m0 / 192;
        const int ob  = m0 % 192;
        float* dst = (sec == 0) ? g_q : g_k;
        const size_t base = (size_t)w * NTOK * C_;
#pragma unroll
        for (int im = 0; im < 2; im++) {
            int mr = wm + im * 16 + (lane >> 2);
            float b0 = qkv_b[m0 + mr];
            float b1 = qkv_b[m0 + mr + 8];
#pragma unroll
            for (int in = 0; in < 8; in++) {
                int n0 = wn + in * 8 + ((lane & 3) << 1);
                dst[base + (size_t)n0 * C_ + ob + mr]            = acc[im][in][0] + b0;
                dst[base + (size_t)(n0 + 1) * C_ + ob + mr]      = acc[im][in][1] + b0;
                dst[base + (size_t)n0 * C_ + ob + mr + 8]        = acc[im][in][2] + b1;
                dst[base + (size_t)(n0 + 1) * C_ + ob + mr + 8]  = acc[im][in][3] + b1;
            }
        }
    } else {
        // ---------------- v path: 1x tf32 ----------------
        uint32_t* As = smq;             // [64][36]
        uint32_t* Bs = As + 64 * 36;    // [32][264]
        const int m0 = 384 + (blockIdx.x - 6) * 64;

        const int arow = wm + (lane & 7) + ((lane & 8) ? 8 : 0);
        const int asel = (lane & 16) ? 4 : 0;

        for (int k0 = 0; k0 < C_; k0 += 32) {
#pragma unroll
            for (int t = tid; t < 512; t += 256) {
                int r = t >> 3, c4 = (t & 7) << 2;
                float4 v = *reinterpret_cast<const float4*>(&qkv_w[(m0 + r) * C_ + k0 + c4]);
                uint4 h;
                h.x = f2tf(v.x); h.y = f2tf(v.y); h.z = f2tf(v.z); h.w = f2tf(v.w);
                *reinterpret_cast<uint4*>(&As[r * 36 + c4]) = h;
            }
#pragma unroll
            for (int t = tid; t < 2048; t += 256) {
                int c = t >> 6, q = t & 63;
                int i = q >> 2, j4 = (q & 3) << 2;
                float4 v = *reinterpret_cast<const float4*>(
                    xw + (size_t)(k0 + c) * IMG + i * 256 + j4);
                uint4 h;
                h.x = f2tf(v.x); h.y = f2tf(v.y); h.z = f2tf(v.z); h.w = f2tf(v.w);
                *reinterpret_cast<uint4*>(&Bs[c * 264 + i * 16 + j4]) = h;
            }
            __syncthreads();

#pragma unroll
            for (int kk = 0; kk < 32; kk += 8) {
                uint32_t a[2][4];
                int awrd = kk + asel;
                ldsm4(a[0], sptr(&As[arow * 36 + awrd]));
                ldsm4(a[1], sptr(&As[(arow + 16) * 36 + awrd]));
#pragma unroll
                for (int in = 0; in < 8; in++) {
                    int col = wn + in * 8 + (lane >> 2);
                    uint32_t bf[2];
                    bf[0] = Bs[(kk + (lane & 3)) * 264 + col];
                    bf[1] = Bs[(kk + 4 + (lane & 3)) * 264 + col];
#pragma unroll
                    for (int im = 0; im < 2; im++) mma8(acc[im][in], a[im], bf);
                }
            }
            __syncthreads();
        }

        const int ob = m0 - 384;
        const size_t base = (size_t)w * NTOK * C_;
#pragma unroll
        for (int im = 0; im < 2; im++) {
            int mr = wm + im * 16 + (lane >> 2);
            float b0 = qkv_b[m0 + mr];
            float b1 = qkv_b[m0 + mr + 8];
#pragma unroll
            for (int in = 0; in < 8; in++) {
                int n0 = wn + in * 8 + ((lane & 3) << 1);
                g_v[base + (size_t)n0 * C_ + ob + mr]            = acc[im][in][0] + b0;
                g_v[base + (size_t)(n0 + 1) * C_ + ob + mr]      = acc[im][in][1] + b0;
                g_v[base + (size_t)n0 * C_ + ob + mr + 8]        = acc[im][in][2] + b1;
                g_v[base + (size_t)(n0 + 1) * C_ + ob + mr + 8]  = acc[im][in][3] + b1;
            }
        }
    }
}

// ===========================================================================
// K2: attention. grid (4, 1024), 512 thr. smem 220160 B.
// Qh/Ql [64][100], Kh/Kl [128][100] packed bf16x2 words, S [64][260].
// V phase reuses K region as tf32 [128][196].
// ===========================================================================
constexpr int QS2 = 100;
constexpr int VSS = 196;
constexpr int SSS = 260;
constexpr size_t SMEM_ATTN_BYTES = (size_t)(2 * 6400 + 2 * 12800 + 16640) * 4;  // 220160

__global__ void __launch_bounds__(512, 1) attn_kernel() {
    extern __shared__ uint32_t sm[];
    uint32_t* Qh  = sm;
    uint32_t* Ql  = sm + 6400;
    uint32_t* Kh  = sm + 12800;
    uint32_t* Kl  = Kh + 12800;
    uint32_t* Ssm = sm + 12800 + 25600;

    const int qb = blockIdx.x, w = blockIdx.y;
    const int tid = threadIdx.x, warp = tid >> 5, lane = tid & 31;
    const size_t wbase = (size_t)w * NTOK * C_;

    // load + split Q block [64 tok][192 ch] -> packed planes
    const float* qsrc = g_q + wbase + (size_t)qb * 64 * C_;
#pragma unroll
    for (int t = tid; t < 64 * 48; t += 512) {
        int r = t / 48, c2 = (t % 48) << 1;
        float4 v = *reinterpret_cast<const float4*>(qsrc + r * C_ + (c2 << 1));
        uint32_t h0, l0, h1, l1;
        splitbf2(v.x, v.y, h0, l0);
        splitbf2(v.z, v.w, h1, l1);
        Qh[r * QS2 + c2] = h0; Qh[r * QS2 + c2 + 1] = h1;
        Ql[r * QS2 + c2] = l0; Ql[r * QS2 + c2 + 1] = l1;
    }

    const int wm = (warp >> 3) << 5;
    const int wk = (warp & 7) << 4;
    const int arow = wm + (lane & 7) + ((lane & 8) ? 8 : 0);
    const int asel = (lane & 16) ? 4 : 0;
    const int brow = wk + (lane & 7) + ((lane & 16) ? 8 : 0);
    const int bsel = (lane & 8) ? 4 : 0;

    // ---- S = Q K^T (3x bf16): two 128-key chunks ----
    for (int cb = 0; cb < 2; cb++) {
        const float* ksrc = g_k + wbase + (size_t)cb * 128 * C_;
#pragma unroll
        for (int t = tid; t < 128 * 48; t += 512) {
            int r = t / 48, c2 = (t % 48) << 1;
            float4 v = *reinterpret_cast<const float4*>(ksrc + r * C_ + (c2 << 1));
            uint32_t h0, l0, h1, l1;
            splitbf2(v.x, v.y, h0, l0);
            splitbf2(v.z, v.w, h1, l1);
            Kh[r * QS2 + c2] = h0; Kh[r * QS2 + c2 + 1] = h1;
            Kl[r * QS2 + c2] = l0; Kl[r * QS2 + c2 + 1] = l1;
        }
        __syncthreads();

        float sacc[2][2][4];
#pragma unroll
        for (int i = 0; i < 2; i++)
#pragma unroll
            for (int j = 0; j < 2; j++)
#pragma unroll
                for (int r = 0; r < 4; r++) sacc[i][j][r] = 0.f;

#pragma unroll
        for (int kk2 = 0; kk2 < 96; kk2 += 8) {
            uint32_t ah[2][4], al[2][4], bh4[4], bl4[4];
            int awrd = kk2 + asel;
            ldsm4(ah[0], sptr(&Qh[arow * QS2 + awrd]));
            ldsm4(ah[1], sptr(&Qh[(arow + 16) * QS2 + awrd]));
            ldsm4(al[0], sptr(&Ql[arow * QS2 + awrd]));
            ldsm4(al[1], sptr(&Ql[(arow + 16) * QS2 + awrd]));
            int bwrd = kk2 + bsel;
            ldsm4(bh4, sptr(&Kh[brow * QS2 + bwrd]));
            ldsm4(bl4, sptr(&Kl[brow * QS2 + bwrd]));
#pragma unroll
            for (int im = 0; im < 2; im++) {
                mma16(sacc[im][0], ah[im], bl4);
                mma16(sacc[im][0], al[im], bh4);
                mma16(sacc[im][0], ah[im], bh4);
                mma16(sacc[im][1], ah[im], bl4 + 2);
                mma16(sacc[im][1], al[im], bh4 + 2);
                mma16(sacc[im][1], ah[im], bh4 + 2);
            }
        }
#pragma unroll
        for (int im = 0; im < 2; im++) {
            int r0 = wm + im * 16 + (lane >> 2);
#pragma unroll
            for (int in = 0; in < 2; in++) {
                int c0 = cb * 128 + wk + in * 8 + ((lane & 3) << 1);
                Ssm[r0 * SSS + c0]           = __float_as_uint(sacc[im][in][0]);
                Ssm[r0 * SSS + c0 + 1]       = __float_as_uint(sacc[im][in][1]);
                Ssm[(r0 + 8) * SSS + c0]     = __float_as_uint(sacc[im][in][2]);
                Ssm[(r0 + 8) * SSS + c0 + 1] = __float_as_uint(sacc[im][in][3]);
            }
        }
        __syncthreads();
    }

    // ---- softmax (16 warps x 4 rows of 256); P stored as tf32 ----
#pragma unroll
    for (int rr = 0; rr < 4; rr++) {
        int row = warp * 4 + rr;
        float v[8];
        float mx = -3.0e38f;
#pragma unroll
        for (int i = 0; i < 8; i++) {
            v[i] = __uint_as_float(Ssm[row * SSS + lane + (i << 5)]);
            mx = fmaxf(mx, v[i]);
        }
#pragma unroll
        for (int off = 16; off; off >>= 1) mx = fmaxf(mx, __shfl_xor_sync(0xffffffffu, mx, off));
        float sum = 0.f;
#pragma unroll
        for (int i = 0; i < 8; i++) { v[i] = __expf(v[i] - mx); sum += v[i]; }
#pragma unroll
        for (int off = 16; off; off >>= 1) sum += __shfl_xor_sync(0xffffffffu, sum, off);
        float inv = 1.0f / sum;
#pragma unroll
        for (int i = 0; i < 8; i++) Ssm[row * SSS + lane + (i << 5)] = f2tf(v[i] * inv);
    }
    __syncthreads();

    // ---- O = P @ V (1x tf32): two 128-token chunks; V in Kh region ----
    const int wc = (warp & 7) * 24;
    float oacc[2][3][4];
#pragma unroll
    for (int i = 0; i < 2; i++)
#pragma unroll
        for (int j = 0; j < 3; j++)
#pragma unroll
            for (int r = 0; r < 4; r++) oacc[i][j][r] = 0.f;

    for (int vb = 0; vb < 2; vb++) {
        const float* vsrc = g_v + wbase + (size_t)vb * 128 * C_;
#pragma unroll
        for (int t = tid; t < 128 * 48; t += 512) {
            int r = t / 48, c4 = (t % 48) << 2;
            float4 v = *reinterpret_cast<const float4*>(vsrc + r * C_ + c4);
            uint32_t* d = &Kh[r * VSS + c4];
            d[0] = f2tf(v.x); d[1] = f2tf(v.y); d[2] = f2tf(v.z); d[3] = f2tf(v.w);
        }
        __syncthreads();

#pragma unroll
        for (int kk = 0; kk < 128; kk += 8) {
            uint32_t a[2][4];
            int awrd = vb * 128 + kk + asel;
            ldsm4(a[0], sptr(&Ssm[arow * SSS + awrd]));
            ldsm4(a[1], sptr(&Ssm[(arow + 16) * SSS + awrd]));
#pragma unroll
            for (int in = 0; in < 3; in++) {
                int col = wc + in * 8 + (lane >> 2);
                uint32_t bf[2];
                bf[0] = Kh[(kk + (lane & 3)) * VSS + col];
                bf[1] = Kh[(kk + 4 + (lane & 3)) * VSS + col];
#pragma unroll
                for (int im = 0; im < 2; im++) mma8(oacc[im][in], a[im], bf);
            }
        }
        __syncthreads();
    }

    const size_t ybase = (size_t)w * C_ * NTOK;
#pragma unroll
    for (int im = 0; im < 2; im++) {
        int q0 = qb * 64 + wm + im * 16 + (lane >> 2);
#pragma unroll
        for (int in = 0; in < 3; in++) {
            int c0 = wc + in * 8 + ((lane & 3) << 1);
            g_y[ybase + (size_t)c0 * NTOK + q0]           = oacc[im][in][0];
            g_y[ybase + (size_t)(c0 + 1) * NTOK + q0]     = oacc[im][in][1];
            g_y[ybase + (size_t)c0 * NTOK + q0 + 8]       = oacc[im][in][2];
            g_y[ybase + (size_t)(c0 + 1) * NTOK + q0 + 8] = oacc[im][in][3];
        }
    }
}

// ===========================================================================
// K3: proj + bias + residual (1x tf32). grid (3, 1024), 256 thr, 2 CTA/SM.
// ===========================================================================
constexpr size_t SMEM_PROJ_BYTES = (size_t)(64 * 36 + 32 * 264) * 4;  // 43008

__global__ void __launch_bounds__(256, 2) proj_kernel(const float* __restrict__ x,
                                                      const float* __restrict__ proj_w,
                                                      const float* __restrict__ proj_b,
                                                      float* __restrict__ out) {
    extern __shared__ uint32_t smp[];
    uint32_t* As = smp;
    uint32_t* Bs = smp + 64 * 36;

    const int m0 = blockIdx.x * 64;
    const int w  = blockIdx.y;
    const int b  = w >> 8, wh = (w >> 4) & 15, ww = w & 15;
    const int tid = threadIdx.x, warp = tid >> 5, lane = tid & 31;
    const int wm = (warp >> 2) << 5, wn = (warp & 3) << 6;
    const int arow = wm + (lane & 7) + ((lane & 8) ? 8 : 0);
    const int asel = (lane & 16) ? 4 : 0;

    float acc[2][8][4];
#pragma unroll
    for (int i = 0; i < 2; i++)
#pragma unroll
        for (int j = 0; j < 8; j++)
#pragma unroll
            for (int r = 0; r < 4; r++) acc[i][j][r] = 0.f;

    const float* ysrc = g_y + (size_t)w * C_ * NTOK;

    for (int k0 = 0; k0 < C_; k0 += 32) {
#pragma unroll
        for (int t = tid; t < 512; t += 256) {
            int r = t >> 3, c4 = (t & 7) << 2;
            float4 v = *reinterpret_cast<const float4*>(&proj_w[(m0 + r) * C_ + k0 + c4]);
            uint4 h;
            h.x = f2tf(v.x); h.y = f2tf(v.y); h.z = f2tf(v.z); h.w = f2tf(v.w);
            *reinterpret_cast<uint4*>(&As[r * 36 + c4]) = h;
        }
#pragma unroll
        for (int t = tid; t < 2048; t += 256) {
            int c = t >> 6, n4 = (t & 63) << 2;
            float4 v = *reinterpret_cast<const float4*>(ysrc + (size_t)(k0 + c) * NTOK + n4);
            uint4 h;
            h.x = f2tf(v.x); h.y = f2tf(v.y); h.z = f2tf(v.z); h.w = f2tf(v.w);
            *reinterpret_cast<uint4*>(&Bs[c * 264 + n4]) = h;
        }
        __syncthreads();

#pragma unroll
        for (int kk = 0; kk < 32; kk += 8) {
            uint32_t a[2][4];
            int awrd = kk + asel;
            ldsm4(a[0], sptr(&As[arow * 36 + awrd]));
            ldsm4(a[1], sptr(&As[(arow + 16) * 36 + awrd]));
#pragma unroll
            for (int in = 0; in < 8; in++) {
                int col = wn + in * 8 + (lane >> 2);
                uint32_t bf[2];
                bf[0] = Bs[(kk + (lane & 3)) * 264 + col];
                bf[1] = Bs[(kk + 4 + (lane & 3)) * 264 + col];
#pragma unroll
                for (int im = 0; im < 2; im++) mma8(acc[im][in], a[im], bf);
            }
        }
        __syncthreads();
    }

#pragma unroll
    for (int im = 0; im < 2; im++) {
        int mr = wm + im * 16 + (lane >> 2);
        int ch = m0 + mr;
        float b0 = proj_b[ch];
        float b1 = proj_b[ch + 8];
#pragma unroll
        for (int in = 0; in < 8; in++) {
            int n0 = wn + in * 8 + ((lane & 3) << 1);
            int i = n0 >> 4, j = n0 & 15;
            size_t g0 = (((size_t)b * C_ + ch) * 256 + wh * 16 + i) * 256 + ww * 16 + j;
            size_t g1 = (((size_t)b * C_ + ch + 8) * 256 + wh * 16 + i) * 256 + ww * 16 + j;
            float2 x0 = *reinterpret_cast<const float2*>(&x[g0]);
            float2 x1 = *reinterpret_cast<const float2*>(&x[g1]);
            float2 r0, r1;
            r0.x = acc[im][in][0] + b0 + x0.x;
            r0.y = acc[im][in][1] + b0 + x0.y;
            r1.x = acc[im][in][2] + b1 + x1.x;
            r1.y = acc[im][in][3] + b1 + x1.y;
            *reinterpret_cast<float2*>(&out[g0]) = r0;
            *reinterpret_cast<float2*>(&out[g1]) = r1;
        }
    }
}

// ---------------------------------------------------------------------------
namespace {
struct WarmUp {
    WarmUp() {
        void* p = nullptr;
        cudaGetSymbolAddress(&p, g_q);
        cudaGetSymbolAddress(&p, g_k);
        cudaGetSymbolAddress(&p, g_v);
        cudaGetSymbolAddress(&p, g_y);
        cudaGetSymbolAddress(&p, g_wqkh);
        cudaGetSymbolAddress(&p, g_wqkl);
        cudaFuncSetAttribute(attn_kernel, cudaFuncAttributeMaxDynamicSharedMemorySize,
                             (int)SMEM_ATTN_BYTES);
        cudaFuncSetAttribute(qkv_kernel, cudaFuncAttributeMaxDynamicSharedMemorySize,
                             (int)SMEM_QKV_BYTES);
        cudaFuncSetAttribute(proj_kernel, cudaFuncAttributeMaxDynamicSharedMemorySize,
                             (int)SMEM_PROJ_BYTES);
    }
};
WarmUp warm_;
}  // namespace

extern "C" void kernel_launch(void* const* d_in, const int* in_sizes, int n_in,
                              void* d_out, int out_size) {
    (void)in_sizes; (void)n_in; (void)out_size;
    const float* x      = (const float*)d_in[0];
    const float* qkv_w  = (const float*)d_in[1];
    const float* qkv_b  = (const float*)d_in[2];
    const float* proj_w = (const float*)d_in[3];
    const float* proj_b = (const float*)d_in[4];
    float* out = (float*)d_out;

    cudaFuncSetAttribute(attn_kernel, cudaFuncAttributeMaxDynamicSharedMemorySize,
                         (int)SMEM_ATTN_BYTES);
    cudaFuncSetAttribute(qkv_kernel, cudaFuncAttributeMaxDynamicSharedMemorySize,
                         (int)SMEM_QKV_BYTES);
    cudaFuncSetAttribute(proj_kernel, cudaFuncAttributeMaxDynamicSharedMemorySize,
                         (int)SMEM_PROJ_BYTES);

    split_w_kernel<<<144, 256>>>(qkv_w);
    qkv_kernel<<<dim3(9, NWIN), 256, SMEM_QKV_BYTES>>>(x, qkv_w, qkv_b);
    attn_kernel<<<dim3(4, NWIN), 512, SMEM_ATTN_BYTES>>>();
    proj_kernel<<<dim3(3, NWIN), 256, SMEM_PROJ_BYTES>>>(x, proj_w, proj_b, out);
}

// round 9
// speedup vs baseline: 1.1074x; 1.0170x over previous
#include <cuda_runtime.h>
#include <cuda_bf16.h>
#include <cstdint>

// ---------------------------------------------------------------------------
// TransformerBlock: windowed attention, B=4 C=192 H=W=256, 16x16 windows.
//   K0 : split W_qk -> bf16 hi/lo packed planes
//   K1 : merged qkv, grid (9, 1024): bx 0-5 q/k (3x bf16), bx 6-8 v (tf32)
//   K2 : attention, grid (4, 1024), 512 thr
//   K3 : proj, grid (3, 1024), 256 thr, 2 CTA/SM
// ldmatrix for ALL mma fragments incl. tf32 B (tiles stored [n][k]).
// Layouts: g_y [win][tok][ch], g_v [win][ch][tok].
// ---------------------------------------------------------------------------

constexpr int C_     = 192;
constexpr int NTOK   = 256;
constexpr int NWIN   = 1024;
constexpr int IMG    = 256 * 256;

__device__ float g_q[(size_t)NWIN * NTOK * C_];
__device__ float g_k[(size_t)NWIN * NTOK * C_];
__device__ float g_v[(size_t)NWIN * C_ * NTOK];   // [win][ch][tok]
__device__ float g_y[(size_t)NWIN * NTOK * C_];   // [win][tok][ch]
__device__ uint32_t g_wqkh[384 * 96];
__device__ uint32_t g_wqkl[384 * 96];

__device__ __forceinline__ uint32_t f2tf(float x) {
    uint32_t u;
    asm("cvt.rna.tf32.f32 %0, %1;" : "=r"(u) : "f"(x));
    return u;
}
__device__ __forceinline__ void splitbf2(float x0, float x1, uint32_t& hi, uint32_t& lo) {
    __nv_bfloat16 h0 = __float2bfloat16_rn(x0);
    __nv_bfloat16 h1 = __float2bfloat16_rn(x1);
    __nv_bfloat16 l0 = __float2bfloat16_rn(x0 - __bfloat162float(h0));
    __nv_bfloat16 l1 = __float2bfloat16_rn(x1 - __bfloat162float(h1));
    hi = ((uint32_t)__bfloat16_as_ushort(h1) << 16) | __bfloat16_as_ushort(h0);
    lo = ((uint32_t)__bfloat16_as_ushort(l1) << 16) | __bfloat16_as_ushort(l0);
}
__device__ __forceinline__ uint32_t sptr(const void* p) {
    return (uint32_t)__cvta_generic_to_shared(p);
}
__device__ __forceinline__ void ldsm4(uint32_t* r, uint32_t a) {
    asm volatile("ldmatrix.sync.aligned.m8n8.x4.shared.b16 {%0,%1,%2,%3}, [%4];"
        : "=r"(r[0]), "=r"(r[1]), "=r"(r[2]), "=r"(r[3]) : "r"(a));
}
__device__ __forceinline__ void ldsm2(uint32_t* r, uint32_t a) {
    asm volatile("ldmatrix.sync.aligned.m8n8.x2.shared.b16 {%0,%1}, [%2];"
        : "=r"(r[0]), "=r"(r[1]) : "r"(a));
}
__device__ __forceinline__ void ldsm4t(uint32_t* r, uint32_t a) {
    asm volatile("ldmatrix.sync.aligned.m8n8.x4.trans.shared.b16 {%0,%1,%2,%3}, [%4];"
        : "=r"(r[0]), "=r"(r[1]), "=r"(r[2]), "=r"(r[3]) : "r"(a));
}
__device__ __forceinline__ void mma8(float* d, const uint32_t* a, const uint32_t* b) {
    asm volatile(
        "mma.sync.aligned.m16n8k8.row.col.f32.tf32.tf32.f32 "
        "{%0,%1,%2,%3}, {%4,%5,%6,%7}, {%8,%9}, {%0,%1,%2,%3};\n"
        : "+f"(d[0]), "+f"(d[1]), "+f"(d[2]), "+f"(d[3])
        : "r"(a[0]), "r"(a[1]), "r"(a[2]), "r"(a[3]),
          "r"(b[0]), "r"(b[1]));
}
__device__ __forceinline__ void mma16(float* d, const uint32_t* a, const uint32_t* b) {
    asm volatile(
        "mma.sync.aligned.m16n8k16.row.col.f32.bf16.bf16.f32 "
        "{%0,%1,%2,%3}, {%4,%5,%6,%7}, {%8,%9}, {%0,%1,%2,%3};\n"
        : "+f"(d[0]), "+f"(d[1]), "+f"(d[2]), "+f"(d[3])
        : "r"(a[0]), "r"(a[1]), "r"(a[2]), "r"(a[3]),
          "r"(b[0]), "r"(b[1]));
}

// ===========================================================================
// K0: split W_qk rows [0,384) into bf16 hi/lo packed planes.
// ===========================================================================
__global__ void split_w_kernel(const float* __restrict__ qkv_w) {
    int idx = blockIdx.x * 256 + threadIdx.x;
    if (idx >= 384 * 96) return;
    int r = idx / 96, c = idx % 96;
    uint32_t h, l;
    splitbf2(qkv_w[r * C_ + 2 * c], qkv_w[r * C_ + 2 * c + 1], h, l);
    g_wqkh[idx] = h;
    g_wqkl[idx] = l;
}

// ===========================================================================
// K1: merged qkv. grid (9, 1024), 256 thr, 2 CTA/SM. smem 44032 B.
// ===========================================================================
constexpr int AS3 = 20;
constexpr int BT16 = 264;
constexpr size_t SMEM_QKV_BYTES = (size_t)(2 * 64 * AS3 + 2 * 32 * 132) * 4;  // 44032

__global__ void __launch_bounds__(256, 2) qkv_kernel(const float* __restrict__ x,
                                                     const float* __restrict__ qkv_w,
                                                     const float* __restrict__ qkv_b) {
    extern __shared__ uint32_t smq[];

    const int w  = blockIdx.y;
    const int b  = w >> 8, wh = (w >> 4) & 15, ww = w & 15;
    const int tid = threadIdx.x, warp = tid >> 5, lane = tid & 31;
    const int wm = (warp >> 2) << 5;
    const int wn = (warp & 3) << 6;
    const float* xw = x + (size_t)b * C_ * IMG + (size_t)(wh * 16) * 256 + ww * 16;

    float acc[2][8][4];
#pragma unroll
    for (int i = 0; i < 2; i++)
#pragma unroll
        for (int j = 0; j < 8; j++)
#pragma unroll
            for (int r = 0; r < 4; r++) acc[i][j][r] = 0.f;

    if (blockIdx.x < 6) {
        // ---------------- q/k path: 3x bf16 ----------------
        uint32_t* Ah = smq;
        uint32_t* Al = Ah + 64 * AS3;
        uint16_t* Bh16 = (uint16_t*)(smq + 2 * 64 * AS3);
        uint16_t* Bl16 = Bh16 + 32 * BT16;
        const int m0 = blockIdx.x * 64;

        const int arow = wm + (lane & 7) + ((lane & 8) ? 8 : 0);
        const int asel = (lane & 16) ? 4 : 0;
        const int brow0 = (lane & 7) + ((lane & 8) ? 8 : 0);
        const int bsel = (lane & 16) ? 8 : 0;

        for (int k0 = 0; k0 < C_; k0 += 32) {
            const int kw0 = k0 >> 1;
#pragma unroll
            for (int t = tid; t < 256; t += 256) {
                int r = t >> 2, c4 = (t & 3) << 2;
                *reinterpret_cast<uint4*>(&Ah[r * AS3 + c4]) =
                    *reinterpret_cast<const uint4*>(&g_wqkh[(m0 + r) * 96 + kw0 + c4]);
                *reinterpret_cast<uint4*>(&Al[r * AS3 + c4]) =
                    *reinterpret_cast<const uint4*>(&g_wqkl[(m0 + r) * 96 + kw0 + c4]);
            }
#pragma unroll
            for (int t = tid; t < 2048; t += 256) {
                int c = t >> 6, q = t & 63;
                int i = q >> 2, j4 = (q & 3) << 2;
                float4 v = *reinterpret_cast<const float4*>(
                    xw + (size_t)(k0 + c) * IMG + i * 256 + j4);
                int tok = i * 16 + j4;
                uint32_t h01, l01, h23, l23;
                splitbf2(v.x, v.y, h01, l01);
                splitbf2(v.z, v.w, h23, l23);
                uint32_t* dh = reinterpret_cast<uint32_t*>(&Bh16[c * BT16 + tok]);
                uint32_t* dl = reinterpret_cast<uint32_t*>(&Bl16[c * BT16 + tok]);
                dh[0] = h01; dh[1] = h23;
                dl[0] = l01; dl[1] = l23;
            }
            __syncthreads();

#pragma unroll
            for (int kk = 0; kk < 32; kk += 16) {
                uint32_t ah[2][4], al[2][4];
                int awrd = (kk >> 1) + asel;
                ldsm4(ah[0], sptr(&Ah[arow * AS3 + awrd]));
                ldsm4(ah[1], sptr(&Ah[(arow + 16) * AS3 + awrd]));
                ldsm4(al[0], sptr(&Al[arow * AS3 + awrd]));
                ldsm4(al[1], sptr(&Al[(arow + 16) * AS3 + awrd]));
                int brow = kk + brow0;
#pragma unroll
                for (int inp = 0; inp < 4; inp++) {
                    int n0 = wn + inp * 16 + bsel;
                    uint32_t bh4[4], bl4[4];
                    ldsm4t(bh4, sptr(&Bh16[brow * BT16 + n0]));
                    ldsm4t(bl4, sptr(&Bl16[brow * BT16 + n0]));
#pragma unroll
                    for (int im = 0; im < 2; im++) {
                        mma16(acc[im][2 * inp],     ah[im], bl4);
                        mma16(acc[im][2 * inp],     al[im], bh4);
                        mma16(acc[im][2 * inp],     ah[im], bh4);
                        mma16(acc[im][2 * inp + 1], ah[im], bl4 + 2);
                        mma16(acc[im][2 * inp + 1], al[im], bh4 + 2);
                        mma16(acc[im][2 * inp + 1], ah[im], bh4 + 2);
                    }
                }
            }
            __syncthreads();
        }

        const int sec = m0 / 192;
        const int ob  = m0 % 192;
        float* dst = (sec == 0) ? g_q : g_k;
        const size_t base = (size_t)w * NTOK * C_;
#pragma unroll
        for (int im = 0; im < 2; im++) {
            int mr = wm + im * 16 + (lane >> 2);
            float b0 = qkv_b[m0 + mr];
            float b1 = qkv_b[m0 + mr + 8];
#pragma unroll
            for (int in = 0; in < 8; in++) {
                int n0 = wn + in * 8 + ((lane & 3) << 1);
                dst[base + (size_t)n0 * C_ + ob + mr]            = acc[im][in][0] + b0;
                dst[base + (size_t)(n0 + 1) * C_ + ob + mr]      = acc[im][in][1] + b0;
                dst[base + (size_t)n0 * C_ + ob + mr + 8]        = acc[im][in][2] + b1;
                dst[base + (size_t)(n0 + 1) * C_ + ob + mr + 8]  = acc[im][in][3] + b1;
            }
        }
    } else {
        // ---------------- v path: 1x tf32, output [ch][tok] ----------------
        uint32_t* As = smq;             // [64][36]
        uint32_t* Bs = As + 64 * 36;    // [32 ch][264 tok]
        const int m0 = 384 + (blockIdx.x - 6) * 64;

        const int arow = wm + (lane & 7) + ((lane & 8) ? 8 : 0);
        const int asel = (lane & 16) ? 4 : 0;

        for (int k0 = 0; k0 < C_; k0 += 32) {
#pragma unroll
            for (int t = tid; t < 512; t += 256) {
                int r = t >> 3, c4 = (t & 7) << 2;
                float4 v = *reinterpret_cast<const float4*>(&qkv_w[(m0 + r) * C_ + k0 + c4]);
                uint4 h;
                h.x = f2tf(v.x); h.y = f2tf(v.y); h.z = f2tf(v.z); h.w = f2tf(v.w);
                *reinterpret_cast<uint4*>(&As[r * 36 + c4]) = h;
            }
#pragma unroll
            for (int t = tid; t < 2048; t += 256) {
                int c = t >> 6, q = t & 63;
                int i = q >> 2, j4 = (q & 3) << 2;
                float4 v = *reinterpret_cast<const float4*>(
                    xw + (size_t)(k0 + c) * IMG + i * 256 + j4);
                uint4 h;
                h.x = f2tf(v.x); h.y = f2tf(v.y); h.z = f2tf(v.z); h.w = f2tf(v.w);
                *reinterpret_cast<uint4*>(&Bs[c * 264 + i * 16 + j4]) = h;
            }
            __syncthreads();

#pragma unroll
            for (int kk = 0; kk < 32; kk += 8) {
                uint32_t a[2][4];
                int awrd = kk + asel;
                ldsm4(a[0], sptr(&As[arow * 36 + awrd]));
                ldsm4(a[1], sptr(&As[(arow + 16) * 36 + awrd]));
#pragma unroll
                for (int in = 0; in < 8; in++) {
                    int col = wn + in * 8 + (lane >> 2);
                    uint32_t bf[2];
                    bf[0] = Bs[(kk + (lane & 3)) * 264 + col];
                    bf[1] = Bs[(kk + 4 + (lane & 3)) * 264 + col];
#pragma unroll
                    for (int im = 0; im < 2; im++) mma8(acc[im][in], a[im], bf);
                }
            }
            __syncthreads();
        }

        const int ob = m0 - 384;
        const size_t base = (size_t)w * C_ * NTOK;   // [ch][tok]
#pragma unroll
        for (int im = 0; im < 2; im++) {
            int mr = wm + im * 16 + (lane >> 2);
            float b0 = qkv_b[m0 + mr];
            float b1 = qkv_b[m0 + mr + 8];
#pragma unroll
            for (int in = 0; in < 8; in++) {
                int n0 = wn + in * 8 + ((lane & 3) << 1);
                float2 r0, r1;
                r0.x = acc[im][in][0] + b0; r0.y = acc[im][in][1] + b0;
                r1.x = acc[im][in][2] + b1; r1.y = acc[im][in][3] + b1;
                *reinterpret_cast<float2*>(&g_v[base + (size_t)(ob + mr) * NTOK + n0])     = r0;
                *reinterpret_cast<float2*>(&g_v[base + (size_t)(ob + mr + 8) * NTOK + n0]) = r1;
            }
        }
    }
}

// ===========================================================================
// K2: attention. grid (4, 1024), 512 thr. smem 220160 B.
// V phase: Vs [192 ch][132 tok words] tf32 in K region, ldmatrix B-frags.
// ===========================================================================
constexpr int QS2 = 100;
constexpr int VS2 = 132;
constexpr int SSS = 260;
constexpr size_t SMEM_ATTN_BYTES = (size_t)(2 * 6400 + 2 * 12800 + 16640) * 4;  // 220160

__global__ void __launch_bounds__(512, 1) attn_kernel() {
    extern __shared__ uint32_t sm[];
    uint32_t* Qh  = sm;
    uint32_t* Ql  = sm + 6400;
    uint32_t* Kh  = sm + 12800;
    uint32_t* Kl  = Kh + 12800;
    uint32_t* Ssm = sm + 12800 + 25600;
    uint32_t* Vs  = Kh;                 // [192][132] = 25344 <= 25600 words

    const int qb = blockIdx.x, w = blockIdx.y;
    const int tid = threadIdx.x, warp = tid >> 5, lane = tid & 31;
    const size_t wbase = (size_t)w * NTOK * C_;

    const float* qsrc = g_q + wbase + (size_t)qb * 64 * C_;
#pragma unroll
    for (int t = tid; t < 64 * 48; t += 512) {
        int r = t / 48, c2 = (t % 48) << 1;
        float4 v = *reinterpret_cast<const float4*>(qsrc + r * C_ + (c2 << 1));
        uint32_t h0, l0, h1, l1;
        splitbf2(v.x, v.y, h0, l0);
        splitbf2(v.z, v.w, h1, l1);
        Qh[r * QS2 + c2] = h0; Qh[r * QS2 + c2 + 1] = h1;
        Ql[r * QS2 + c2] = l0; Ql[r * QS2 + c2 + 1] = l1;
    }

    const int wm = (warp >> 3) << 5;
    const int wk = (warp & 7) << 4;
    const int arow = wm + (lane & 7) + ((lane & 8) ? 8 : 0);
    const int asel = (lane & 16) ? 4 : 0;
    const int brow = wk + (lane & 7) + ((lane & 16) ? 8 : 0);
    const int bsel = (lane & 8) ? 4 : 0;

    // ---- S = Q K^T (3x bf16): two 128-key chunks ----
    for (int cb = 0; cb < 2; cb++) {
        const float* ksrc = g_k + wbase + (size_t)cb * 128 * C_;
#pragma unroll
        for (int t = tid; t < 128 * 48; t += 512) {
            int r = t / 48, c2 = (t % 48) << 1;
            float4 v = *reinterpret_cast<const float4*>(ksrc + r * C_ + (c2 << 1));
            uint32_t h0, l0, h1, l1;
            splitbf2(v.x, v.y, h0, l0);
            splitbf2(v.z, v.w, h1, l1);
            Kh[r * QS2 + c2] = h0; Kh[r * QS2 + c2 + 1] = h1;
            Kl[r * QS2 + c2] = l0; Kl[r * QS2 + c2 + 1] = l1;
        }
        __syncthreads();

        float sacc[2][2][4];
#pragma unroll
        for (int i = 0; i < 2; i++)
#pragma unroll
            for (int j = 0; j < 2; j++)
#pragma unroll
                for (int r = 0; r < 4; r++) sacc[i][j][r] = 0.f;

#pragma unroll
        for (int kk2 = 0; kk2 < 96; kk2 += 8) {
            uint32_t ah[2][4], al[2][4], bh4[4], bl4[4];
            int awrd = kk2 + asel;
            ldsm4(ah[0], sptr(&Qh[arow * QS2 + awrd]));
            ldsm4(ah[1], sptr(&Qh[(arow + 16) * QS2 + awrd]));
            ldsm4(al[0], sptr(&Ql[arow * QS2 + awrd]));
            ldsm4(al[1], sptr(&Ql[(arow + 16) * QS2 + awrd]));
            int bwrd = kk2 + bsel;
            ldsm4(bh4, sptr(&Kh[brow * QS2 + bwrd]));
            ldsm4(bl4, sptr(&Kl[brow * QS2 + bwrd]));
#pragma unroll
            for (int im = 0; im < 2; im++) {
                mma16(sacc[im][0], ah[im], bl4);
                mma16(sacc[im][0], al[im], bh4);
                mma16(sacc[im][0], ah[im], bh4);
                mma16(sacc[im][1], ah[im], bl4 + 2);
                mma16(sacc[im][1], al[im], bh4 + 2);
                mma16(sacc[im][1], ah[im], bh4 + 2);
            }
        }
#pragma unroll
        for (int im = 0; im < 2; im++) {
            int r0 = wm + im * 16 + (lane >> 2);
#pragma unroll
            for (int in = 0; in < 2; in++) {
                int c0 = cb * 128 + wk + in * 8 + ((lane & 3) << 1);
                Ssm[r0 * SSS + c0]           = __float_as_uint(sacc[im][in][0]);
                Ssm[r0 * SSS + c0 + 1]       = __float_as_uint(sacc[im][in][1]);
                Ssm[(r0 + 8) * SSS + c0]     = __float_as_uint(sacc[im][in][2]);
                Ssm[(r0 + 8) * SSS + c0 + 1] = __float_as_uint(sacc[im][in][3]);
            }
        }
        __syncthreads();
    }

    // ---- softmax (16 warps x 4 rows of 256); P stored as tf32 ----
#pragma unroll
    for (int rr = 0; rr < 4; rr++) {
        int row = warp * 4 + rr;
        float v[8];
        float mx = -3.0e38f;
#pragma unroll
        for (int i = 0; i < 8; i++) {
            v[i] = __uint_as_float(Ssm[row * SSS + lane + (i << 5)]);
            mx = fmaxf(mx, v[i]);
        }
#pragma unroll
        for (int off = 16; off; off >>= 1) mx = fmaxf(mx, __shfl_xor_sync(0xffffffffu, mx, off));
        float sum = 0.f;
#pragma unroll
        for (int i = 0; i < 8; i++) { v[i] = __expf(v[i] - mx); sum += v[i]; }
#pragma unroll
        for (int off = 16; off; off >>= 1) sum += __shfl_xor_sync(0xffffffffu, sum, off);
        float inv = 1.0f / sum;
#pragma unroll
        for (int i = 0; i < 8; i++) Ssm[row * SSS + lane + (i << 5)] = f2tf(v[i] * inv);
    }
    __syncthreads();

    // ---- O = P @ V (1x tf32): two 128-token chunks, ldmatrix B ----
    const int wc = (warp & 7) * 24;
    const int vrow = (lane & 7) + ((lane & 16) ? 8 : 0);
    const int vkw  = (lane & 8) ? 4 : 0;
    float oacc[2][3][4];
#pragma unroll
    for (int i = 0; i < 2; i++)
#pragma unroll
        for (int j = 0; j < 3; j++)
#pragma unroll
            for (int r = 0; r < 4; r++) oacc[i][j][r] = 0.f;

    const size_t vbase = (size_t)w * C_ * NTOK;    // g_v [ch][tok]
    for (int vb = 0; vb < 2; vb++) {
#pragma unroll
        for (int t = tid; t < 192 * 32; t += 512) {
            int ch = t >> 5, t4 = (t & 31) << 2;
            float4 v = *reinterpret_cast<const float4*>(
                g_v + vbase + (size_t)ch * NTOK + vb * 128 + t4);
            uint32_t* d = &Vs[ch * VS2 + t4];
            d[0] = f2tf(v.x); d[1] = f2tf(v.y); d[2] = f2tf(v.z); d[3] = f2tf(v.w);
        }
        __syncthreads();

#pragma unroll
        for (int kk = 0; kk < 128; kk += 8) {
            uint32_t a[2][4], b4[4], b2[2];
            int awrd = vb * 128 + kk + asel;
            ldsm4(a[0], sptr(&Ssm[arow * SSS + awrd]));
            ldsm4(a[1], sptr(&Ssm[(arow + 16) * SSS + awrd]));
            ldsm4(b4, sptr(&Vs[(wc + vrow) * VS2 + kk + vkw]));
            ldsm2(b2, sptr(&Vs[(wc + 16 + (lane & 7)) * VS2 + kk + vkw]));
#pragma unroll
            for (int im = 0; im < 2; im++) {
                mma8(oacc[im][0], a[im], b4);
                mma8(oacc[im][1], a[im], b4 + 2);
                mma8(oacc[im][2], a[im], b2);
            }
        }
        __syncthreads();
    }

    // write O -> g_y [win][tok][ch]
    const size_t ybase = (size_t)w * NTOK * C_;
#pragma unroll
    for (int im = 0; im < 2; im++) {
        int q0 = qb * 64 + wm + im * 16 + (lane >> 2);
#pragma unroll
        for (int in = 0; in < 3; in++) {
            int c0 = wc + in * 8 + ((lane & 3) << 1);
            float2 r0, r1;
            r0.x = oacc[im][in][0]; r0.y = oacc[im][in][1];
            r1.x = oacc[im][in][2]; r1.y = oacc[im][in][3];
            *reinterpret_cast<float2*>(&g_y[ybase + (size_t)q0 * C_ + c0])       = r0;
            *reinterpret_cast<float2*>(&g_y[ybase + (size_t)(q0 + 8) * C_ + c0]) = r1;
        }
    }
}

// ===========================================================================
// K3: proj + bias + residual (1x tf32). grid (3, 1024), 256 thr, 2 CTA/SM.
// B tile [256 tok][36 ch-words] from g_y [tok][ch]; ldmatrix B-frags.
// ===========================================================================
constexpr size_t SMEM_PROJ_BYTES = (size_t)(64 * 36 + 256 * 36) * 4;  // 46080

__global__ void __launch_bounds__(256, 2) proj_kernel(const float* __restrict__ x,
                                                      const float* __restrict__ proj_w,
                                                      const float* __restrict__ proj_b,
                                                      float* __restrict__ out) {
    extern __shared__ uint32_t smp[];
    uint32_t* As = smp;             // [64][36]
    uint32_t* Bs = smp + 64 * 36;   // [256 tok][36]

    const int m0 = blockIdx.x * 64;
    const int w  = blockIdx.y;
    const int b  = w >> 8, wh = (w >> 4) & 15, ww = w & 15;
    const int tid = threadIdx.x, warp = tid >> 5, lane = tid & 31;
    const int wm = (warp >> 2) << 5, wn = (warp & 3) << 6;
    const int arow = wm + (lane & 7) + ((lane & 8) ? 8 : 0);
    const int asel = (lane & 16) ? 4 : 0;
    const int brow8 = (lane & 7) + ((lane & 16) ? 8 : 0);
    const int bkw = (lane & 8) ? 4 : 0;

    float acc[2][8][4];
#pragma unroll
    for (int i = 0; i < 2; i++)
#pragma unroll
        for (int j = 0; j < 8; j++)
#pragma unroll
            for (int r = 0; r < 4; r++) acc[i][j][r] = 0.f;

    const float* ysrc = g_y + (size_t)w * NTOK * C_;   // [tok][ch]

    for (int k0 = 0; k0 < C_; k0 += 32) {
#pragma unroll
        for (int t = tid; t < 512; t += 256) {
            int r = t >> 3, c4 = (t & 7) << 2;
            float4 v = *reinterpret_cast<const float4*>(&proj_w[(m0 + r) * C_ + k0 + c4]);
            uint4 h;
            h.x = f2tf(v.x); h.y = f2tf(v.y); h.z = f2tf(v.z); h.w = f2tf(v.w);
            *reinterpret_cast<uint4*>(&As[r * 36 + c4]) = h;
        }
#pragma unroll
        for (int t = tid; t < 2048; t += 256) {
            int tok = t >> 3, c4 = (t & 7) << 2;
            float4 v = *reinterpret_cast<const float4*>(ysrc + (size_t)tok * C_ + k0 + c4);
            uint4 h;
            h.x = f2tf(v.x); h.y = f2tf(v.y); h.z = f2tf(v.z); h.w = f2tf(v.w);
            *reinterpret_cast<uint4*>(&Bs[tok * 36 + c4]) = h;
        }
        __syncthreads();

#pragma unroll
        for (int kk = 0; kk < 32; kk += 8) {
            uint32_t a[2][4];
            int awrd = kk + asel;
            ldsm4(a[0], sptr(&As[arow * 36 + awrd]));
            ldsm4(a[1], sptr(&As[(arow + 16) * 36 + awrd]));
#pragma unroll
            for (int inp = 0; inp < 4; inp++) {
                int nb = wn + inp * 16;
                uint32_t b4[4];
                ldsm4(b4, sptr(&Bs[(nb + brow8) * 36 + kk + bkw]));
#pragma unroll
                for (int im = 0; im < 2; im++) {
                    mma8(acc[im][2 * inp],     a[im], b4);
                    mma8(acc[im][2 * inp + 1], a[im], b4 + 2);
                }
            }
        }
        __syncthreads();
    }

#pragma unroll
    for (int im = 0; im < 2; im++) {
        int mr = wm + im * 16 + (lane >> 2);
        int ch = m0 + mr;
        float b0 = proj_b[ch];
        float b1 = proj_b[ch + 8];
#pragma unroll
        for (int in = 0; in < 8; in++) {
            int n0 = wn + in * 8 + ((lane & 3) << 1);
            int i = n0 >> 4, j = n0 & 15;
            size_t g0 = (((size_t)b * C_ + ch) * 256 + wh * 16 + i) * 256 + ww * 16 + j;
            size_t g1 = (((size_t)b * C_ + ch + 8) * 256 + wh * 16 + i) * 256 + ww * 16 + j;
            float2 x0 = *reinterpret_cast<const float2*>(&x[g0]);
            float2 x1 = *reinterpret_cast<const float2*>(&x[g1]);
            float2 r0, r1;
            r0.x = acc[im][in][0] + b0 + x0.x;
            r0.y = acc[im][in][1] + b0 + x0.y;
            r1.x = acc[im][in][2] + b1 + x1.x;
            r1.y = acc[im][in][3] + b1 + x1.y;
            *reinterpret_cast<float2*>(&out[g0]) = r0;
            *reinterpret_cast<float2*>(&out[g1]) = r1;
        }
    }
}

// ---------------------------------------------------------------------------
namespace {
struct WarmUp {
    WarmUp() {
        void* p = nullptr;
        cudaGetSymbolAddress(&p, g_q);
        cudaGetSymbolAddress(&p, g_k);
        cudaGetSymbolAddress(&p, g_v);
        cudaGetSymbolAddress(&p, g_y);
        cudaGetSymbolAddress(&p, g_wqkh);
        cudaGetSymbolAddress(&p, g_wqkl);
        cudaFuncSetAttribute(attn_kernel, cudaFuncAttributeMaxDynamicSharedMemorySize,
                             (int)SMEM_ATTN_BYTES);
        cudaFuncSetAttribute(qkv_kernel, cudaFuncAttributeMaxDynamicSharedMemorySize,
                             (int)SMEM_QKV_BYTES);
        cudaFuncSetAttribute(proj_kernel, cudaFuncAttributeMaxDynamicSharedMemorySize,
                             (int)SMEM_PROJ_BYTES);
    }
};
WarmUp warm_;
}  // namespace

extern "C" void kernel_launch(void* const* d_in, const int* in_sizes, int n_in,
                              void* d_out, int out_size) {
    (void)in_sizes; (void)n_in; (void)out_size;
    const float* x      = (const float*)d_in[0];
    const float* qkv_w  = (const float*)d_in[1];
    const float* qkv_b  = (const float*)d_in[2];
    const float* proj_w = (const float*)d_in[3];
    const float* proj_b = (const float*)d_in[4];
    float* out = (float*)d_out;

    cudaFuncSetAttribute(attn_kernel, cudaFuncAttributeMaxDynamicSharedMemorySize,
                         (int)SMEM_ATTN_BYTES);
    cudaFuncSetAttribute(qkv_kernel, cudaFuncAttributeMaxDynamicSharedMemorySize,
                         (int)SMEM_QKV_BYTES);
    cudaFuncSetAttribute(proj_kernel, cudaFuncAttributeMaxDynamicSharedMemorySize,
                         (int)SMEM_PROJ_BYTES);

    split_w_kernel<<<144, 256>>>(qkv_w);
    qkv_kernel<<<dim3(9, NWIN), 256, SMEM_QKV_BYTES>>>(x, qkv_w, qkv_b);
    attn_kernel<<<dim3(4, NWIN), 512, SMEM_ATTN_BYTES>>>();
    proj_kernel<<<dim3(3, NWIN), 256, SMEM_PROJ_BYTES>>>(x, proj_w, proj_b, out);
}

// round 10
// speedup vs baseline: 1.1207x; 1.0120x over previous
#include <cuda_runtime.h>
#include <cuda_bf16.h>
#include <cstdint>

// ---------------------------------------------------------------------------
// TransformerBlock: windowed attention, B=4 C=192 H=W=256, 16x16 windows.
//   K0 : split W_qk -> bf16 hi/lo packed planes
//   K1 : merged qkv, grid (9, 1024): bx 0-5 q/k (3x bf16), bx 6-8 v (tf32)
//   K2 : attention + FUSED PROJ, grid (4, 1024), 512 thr:
//        S=QK^T (3x bf16) ; softmax ; O=PV (tf32) ; out=W_proj@O+b+x (tf32)
// g_y eliminated. ldmatrix for all mma fragments.
// ---------------------------------------------------------------------------

constexpr int C_     = 192;
constexpr int NTOK   = 256;
constexpr int NWIN   = 1024;
constexpr int IMG    = 256 * 256;

__device__ float g_q[(size_t)NWIN * NTOK * C_];
__device__ float g_k[(size_t)NWIN * NTOK * C_];
__device__ float g_v[(size_t)NWIN * C_ * NTOK];   // [win][ch][tok]
__device__ uint32_t g_wqkh[384 * 96];
__device__ uint32_t g_wqkl[384 * 96];

__device__ __forceinline__ uint32_t f2tf(float x) {
    uint32_t u;
    asm("cvt.rna.tf32.f32 %0, %1;" : "=r"(u) : "f"(x));
    return u;
}
__device__ __forceinline__ void splitbf2(float x0, float x1, uint32_t& hi, uint32_t& lo) {
    __nv_bfloat16 h0 = __float2bfloat16_rn(x0);
    __nv_bfloat16 h1 = __float2bfloat16_rn(x1);
    __nv_bfloat16 l0 = __float2bfloat16_rn(x0 - __bfloat162float(h0));
    __nv_bfloat16 l1 = __float2bfloat16_rn(x1 - __bfloat162float(h1));
    hi = ((uint32_t)__bfloat16_as_ushort(h1) << 16) | __bfloat16_as_ushort(h0);
    lo = ((uint32_t)__bfloat16_as_ushort(l1) << 16) | __bfloat16_as_ushort(l0);
}
__device__ __forceinline__ uint32_t sptr(const void* p) {
    return (uint32_t)__cvta_generic_to_shared(p);
}
__device__ __forceinline__ void ldsm4(uint32_t* r, uint32_t a) {
    asm volatile("ldmatrix.sync.aligned.m8n8.x4.shared.b16 {%0,%1,%2,%3}, [%4];"
        : "=r"(r[0]), "=r"(r[1]), "=r"(r[2]), "=r"(r[3]) : "r"(a));
}
__device__ __forceinline__ void ldsm2(uint32_t* r, uint32_t a) {
    asm volatile("ldmatrix.sync.aligned.m8n8.x2.shared.b16 {%0,%1}, [%2];"
        : "=r"(r[0]), "=r"(r[1]) : "r"(a));
}
__device__ __forceinline__ void ldsm4t(uint32_t* r, uint32_t a) {
    asm volatile("ldmatrix.sync.aligned.m8n8.x4.trans.shared.b16 {%0,%1,%2,%3}, [%4];"
        : "=r"(r[0]), "=r"(r[1]), "=r"(r[2]), "=r"(r[3]) : "r"(a));
}
__device__ __forceinline__ void mma8(float* d, const uint32_t* a, const uint32_t* b) {
    asm volatile(
        "mma.sync.aligned.m16n8k8.row.col.f32.tf32.tf32.f32 "
        "{%0,%1,%2,%3}, {%4,%5,%6,%7}, {%8,%9}, {%0,%1,%2,%3};\n"
        : "+f"(d[0]), "+f"(d[1]), "+f"(d[2]), "+f"(d[3])
        : "r"(a[0]), "r"(a[1]), "r"(a[2]), "r"(a[3]),
          "r"(b[0]), "r"(b[1]));
}
__device__ __forceinline__ void mma16(float* d, const uint32_t* a, const uint32_t* b) {
    asm volatile(
        "mma.sync.aligned.m16n8k16.row.col.f32.bf16.bf16.f32 "
        "{%0,%1,%2,%3}, {%4,%5,%6,%7}, {%8,%9}, {%0,%1,%2,%3};\n"
        : "+f"(d[0]), "+f"(d[1]), "+f"(d[2]), "+f"(d[3])
        : "r"(a[0]), "r"(a[1]), "r"(a[2]), "r"(a[3]),
          "r"(b[0]), "r"(b[1]));
}

// ===========================================================================
// K0: split W_qk rows [0,384) into bf16 hi/lo packed planes.
// ===========================================================================
__global__ void split_w_kernel(const float* __restrict__ qkv_w) {
    int idx = blockIdx.x * 256 + threadIdx.x;
    if (idx >= 384 * 96) return;
    int r = idx / 96, c = idx % 96;
    uint32_t h, l;
    splitbf2(qkv_w[r * C_ + 2 * c], qkv_w[r * C_ + 2 * c + 1], h, l);
    g_wqkh[idx] = h;
    g_wqkl[idx] = l;
}

// ===========================================================================
// K1: merged qkv. grid (9, 1024), 256 thr, 2 CTA/SM. smem 44032 B.
// ===========================================================================
constexpr int AS3 = 20;
constexpr int BT16 = 264;
constexpr size_t SMEM_QKV_BYTES = (size_t)(2 * 64 * AS3 + 2 * 32 * 132) * 4;  // 44032

__global__ void __launch_bounds__(256, 2) qkv_kernel(const float* __restrict__ x,
                                                     const float* __restrict__ qkv_w,
                                                     const float* __restrict__ qkv_b) {
    extern __shared__ uint32_t smq[];

    const int w  = blockIdx.y;
    const int b  = w >> 8, wh = (w >> 4) & 15, ww = w & 15;
    const int tid = threadIdx.x, warp = tid >> 5, lane = tid & 31;
    const int wm = (warp >> 2) << 5;
    const int wn = (warp & 3) << 6;
    const float* xw = x + (size_t)b * C_ * IMG + (size_t)(wh * 16) * 256 + ww * 16;

    float acc[2][8][4];
#pragma unroll
    for (int i = 0; i < 2; i++)
#pragma unroll
        for (int j = 0; j < 8; j++)
#pragma unroll
            for (int r = 0; r < 4; r++) acc[i][j][r] = 0.f;

    if (blockIdx.x < 6) {
        // ---------------- q/k path: 3x bf16 ----------------
        uint32_t* Ah = smq;
        uint32_t* Al = Ah + 64 * AS3;
        uint16_t* Bh16 = (uint16_t*)(smq + 2 * 64 * AS3);
        uint16_t* Bl16 = Bh16 + 32 * BT16;
        const int m0 = blockIdx.x * 64;

        const int arow = wm + (lane & 7) + ((lane & 8) ? 8 : 0);
        const int asel = (lane & 16) ? 4 : 0;
        const int brow0 = (lane & 7) + ((lane & 8) ? 8 : 0);
        const int bsel = (lane & 16) ? 8 : 0;

        for (int k0 = 0; k0 < C_; k0 += 32) {
            const int kw0 = k0 >> 1;
#pragma unroll
            for (int t = tid; t < 256; t += 256) {
                int r = t >> 2, c4 = (t & 3) << 2;
                *reinterpret_cast<uint4*>(&Ah[r * AS3 + c4]) =
                    *reinterpret_cast<const uint4*>(&g_wqkh[(m0 + r) * 96 + kw0 + c4]);
                *reinterpret_cast<uint4*>(&Al[r * AS3 + c4]) =
                    *reinterpret_cast<const uint4*>(&g_wqkl[(m0 + r) * 96 + kw0 + c4]);
            }
#pragma unroll
            for (int t = tid; t < 2048; t += 256) {
                int c = t >> 6, q = t & 63;
                int i = q >> 2, j4 = (q & 3) << 2;
                float4 v = *reinterpret_cast<const float4*>(
                    xw + (size_t)(k0 + c) * IMG + i * 256 + j4);
                int tok = i * 16 + j4;
                uint32_t h01, l01, h23, l23;
                splitbf2(v.x, v.y, h01, l01);
                splitbf2(v.z, v.w, h23, l23);
                uint32_t* dh = reinterpret_cast<uint32_t*>(&Bh16[c * BT16 + tok]);
                uint32_t* dl = reinterpret_cast<uint32_t*>(&Bl16[c * BT16 + tok]);
                dh[0] = h01; dh[1] = h23;
                dl[0] = l01; dl[1] = l23;
            }
            __syncthreads();

#pragma unroll
            for (int kk = 0; kk < 32; kk += 16) {
                uint32_t ah[2][4], al[2][4];
                int awrd = (kk >> 1) + asel;
                ldsm4(ah[0], sptr(&Ah[arow * AS3 + awrd]));
                ldsm4(ah[1], sptr(&Ah[(arow + 16) * AS3 + awrd]));
                ldsm4(al[0], sptr(&Al[arow * AS3 + awrd]));
                ldsm4(al[1], sptr(&Al[(arow + 16) * AS3 + awrd]));
                int brow = kk + brow0;
#pragma unroll
                for (int inp = 0; inp < 4; inp++) {
                    int n0 = wn + inp * 16 + bsel;
                    uint32_t bh4[4], bl4[4];
                    ldsm4t(bh4, sptr(&Bh16[brow * BT16 + n0]));
                    ldsm4t(bl4, sptr(&Bl16[brow * BT16 + n0]));
#pragma unroll
                    for (int im = 0; im < 2; im++) {
                        mma16(acc[im][2 * inp],     ah[im], bl4);
                        mma16(acc[im][2 * inp],     al[im], bh4);
                        mma16(acc[im][2 * inp],     ah[im], bh4);
                        mma16(acc[im][2 * inp + 1], ah[im], bl4 + 2);
                        mma16(acc[im][2 * inp + 1], al[im], bh4 + 2);
                        mma16(acc[im][2 * inp + 1], ah[im], bh4 + 2);
                    }
                }
            }
            __syncthreads();
        }

        const int sec = m0 / 192;
        const int ob  = m0 % 192;
        float* dst = (sec == 0) ? g_q : g_k;
        const size_t base = (size_t)w * NTOK * C_;
#pragma unroll
        for (int im = 0; im < 2; im++) {
            int mr = wm + im * 16 + (lane >> 2);
            float b0 = qkv_b[m0 + mr];
            float b1 = qkv_b[m0 + mr + 8];
#pragma unroll
            for (int in = 0; in < 8; in++) {
                int n0 = wn + in * 8 + ((lane & 3) << 1);
                dst[base + (size_t)n0 * C_ + ob + mr]            = acc[im][in][0] + b0;
                dst[base + (size_t)(n0 + 1) * C_ + ob + mr]      = acc[im][in][1] + b0;
                dst[base + (size_t)n0 * C_ + ob + mr + 8]        = acc[im][in][2] + b1;
                dst[base + (size_t)(n0 + 1) * C_ + ob + mr + 8]  = acc[im][in][3] + b1;
            }
        }
    } else {
        // ---------------- v path: 1x tf32, output [ch][tok] ----------------
        uint32_t* As = smq;
        uint32_t* Bs = As + 64 * 36;
        const int m0 = 384 + (blockIdx.x - 6) * 64;

        const int arow = wm + (lane & 7) + ((lane & 8) ? 8 : 0);
        const int asel = (lane & 16) ? 4 : 0;

        for (int k0 = 0; k0 < C_; k0 += 32) {
#pragma unroll
            for (int t = tid; t < 512; t += 256) {
                int r = t >> 3, c4 = (t & 7) << 2;
                float4 v = *reinterpret_cast<const float4*>(&qkv_w[(m0 + r) * C_ + k0 + c4]);
                uint4 h;
                h.x = f2tf(v.x); h.y = f2tf(v.y); h.z = f2tf(v.z); h.w = f2tf(v.w);
                *reinterpret_cast<uint4*>(&As[r * 36 + c4]) = h;
            }
#pragma unroll
            for (int t = tid; t < 2048; t += 256) {
                int c = t >> 6, q = t & 63;
                int i = q >> 2, j4 = (q & 3) << 2;
                float4 v = *reinterpret_cast<const float4*>(
                    xw + (size_t)(k0 + c) * IMG + i * 256 + j4);
                uint4 h;
                h.x = f2tf(v.x); h.y = f2tf(v.y); h.z = f2tf(v.z); h.w = f2tf(v.w);
                *reinterpret_cast<uint4*>(&Bs[c * 264 + i * 16 + j4]) = h;
            }
            __syncthreads();

#pragma unroll
            for (int kk = 0; kk < 32; kk += 8) {
                uint32_t a[2][4];
                int awrd = kk + asel;
                ldsm4(a[0], sptr(&As[arow * 36 + awrd]));
                ldsm4(a[1], sptr(&As[(arow + 16) * 36 + awrd]));
#pragma unroll
                for (int in = 0; in < 8; in++) {
                    int col = wn + in * 8 + (lane >> 2);
                    uint32_t bf[2];
                    bf[0] = Bs[(kk + (lane & 3)) * 264 + col];
                    bf[1] = Bs[(kk + 4 + (lane & 3)) * 264 + col];
#pragma unroll
                    for (int im = 0; im < 2; im++) mma8(acc[im][in], a[im], bf);
                }
            }
            __syncthreads();
        }

        const int ob = m0 - 384;
        const size_t base = (size_t)w * C_ * NTOK;
#pragma unroll
        for (int im = 0; im < 2; im++) {
            int mr = wm + im * 16 + (lane >> 2);
            float b0 = qkv_b[m0 + mr];
            float b1 = qkv_b[m0 + mr + 8];
#pragma unroll
            for (int in = 0; in < 8; in++) {
                int n0 = wn + in * 8 + ((lane & 3) << 1);
                float2 r0, r1;
                r0.x = acc[im][in][0] + b0; r0.y = acc[im][in][1] + b0;
                r1.x = acc[im][in][2] + b1; r1.y = acc[im][in][3] + b1;
                *reinterpret_cast<float2*>(&g_v[base + (size_t)(ob + mr) * NTOK + n0])     = r0;
                *reinterpret_cast<float2*>(&g_v[base + (size_t)(ob + mr + 8) * NTOK + n0]) = r1;
            }
        }
    }
}

// ===========================================================================
// K2: attention + fused proj. grid (4, 1024), 512 thr. smem 220160 B.
// Regions (words): Qh[0,6400) Ql[6400,12800) Kh[12800,25600) Kl[25600,38400)
//                  Ssm[38400,55040)
// V phase: Vs = Kh region as [192][132].
// Proj phase (after PV): Osm[64][196] at 0, Wsm[192][196] at 12544.
// ===========================================================================
constexpr int QS2 = 100;
constexpr int VS2 = 132;
constexpr int SSS = 260;
constexpr int OS2 = 196;
constexpr size_t SMEM_ATTN_BYTES = (size_t)(2 * 6400 + 2 * 12800 + 16640) * 4;  // 220160

__global__ void __launch_bounds__(512, 1) attn_kernel(const float* __restrict__ x,
                                                      const float* __restrict__ proj_w,
                                                      const float* __restrict__ proj_b,
                                                      float* __restrict__ out) {
    extern __shared__ uint32_t sm[];
    uint32_t* Qh  = sm;
    uint32_t* Ql  = sm + 6400;
    uint32_t* Kh  = sm + 12800;
    uint32_t* Kl  = Kh + 12800;
    uint32_t* Ssm = sm + 12800 + 25600;
    uint32_t* Vs  = Kh;                 // [192][132] during PV
    uint32_t* Osm = sm;                 // [64][196] proj phase (12544 w)
    uint32_t* Wsm = sm + 12544;         // [192][196] proj phase (37632 w)

    const int qb = blockIdx.x, w = blockIdx.y;
    const int b  = w >> 8, wh = (w >> 4) & 15, ww = w & 15;
    const int tid = threadIdx.x, warp = tid >> 5, lane = tid & 31;
    const size_t wbase = (size_t)w * NTOK * C_;

    const float* qsrc = g_q + wbase + (size_t)qb * 64 * C_;
#pragma unroll
    for (int t = tid; t < 64 * 48; t += 512) {
        int r = t / 48, c2 = (t % 48) << 1;
        float4 v = *reinterpret_cast<const float4*>(qsrc + r * C_ + (c2 << 1));
        uint32_t h0, l0, h1, l1;
        splitbf2(v.x, v.y, h0, l0);
        splitbf2(v.z, v.w, h1, l1);
        Qh[r * QS2 + c2] = h0; Qh[r * QS2 + c2 + 1] = h1;
        Ql[r * QS2 + c2] = l0; Ql[r * QS2 + c2 + 1] = l1;
    }

    const int wm = (warp >> 3) << 5;
    const int wk = (warp & 7) << 4;
    const int arow = wm + (lane & 7) + ((lane & 8) ? 8 : 0);
    const int asel = (lane & 16) ? 4 : 0;
    const int brow = wk + (lane & 7) + ((lane & 16) ? 8 : 0);
    const int bsel = (lane & 8) ? 4 : 0;

    // ---- S = Q K^T (3x bf16): two 128-key chunks ----
    for (int cb = 0; cb < 2; cb++) {
        const float* ksrc = g_k + wbase + (size_t)cb * 128 * C_;
#pragma unroll
        for (int t = tid; t < 128 * 48; t += 512) {
            int r = t / 48, c2 = (t % 48) << 1;
            float4 v = *reinterpret_cast<const float4*>(ksrc + r * C_ + (c2 << 1));
            uint32_t h0, l0, h1, l1;
            splitbf2(v.x, v.y, h0, l0);
            splitbf2(v.z, v.w, h1, l1);
            Kh[r * QS2 + c2] = h0; Kh[r * QS2 + c2 + 1] = h1;
            Kl[r * QS2 + c2] = l0; Kl[r * QS2 + c2 + 1] = l1;
        }
        __syncthreads();

        float sacc[2][2][4];
#pragma unroll
        for (int i = 0; i < 2; i++)
#pragma unroll
            for (int j = 0; j < 2; j++)
#pragma unroll
                for (int r = 0; r < 4; r++) sacc[i][j][r] = 0.f;

#pragma unroll
        for (int kk2 = 0; kk2 < 96; kk2 += 8) {
            uint32_t ah[2][4], al[2][4], bh4[4], bl4[4];
            int awrd = kk2 + asel;
            ldsm4(ah[0], sptr(&Qh[arow * QS2 + awrd]));
            ldsm4(ah[1], sptr(&Qh[(arow + 16) * QS2 + awrd]));
            ldsm4(al[0], sptr(&Ql[arow * QS2 + awrd]));
            ldsm4(al[1], sptr(&Ql[(arow + 16) * QS2 + awrd]));
            int bwrd = kk2 + bsel;
            ldsm4(bh4, sptr(&Kh[brow * QS2 + bwrd]));
            ldsm4(bl4, sptr(&Kl[brow * QS2 + bwrd]));
#pragma unroll
            for (int im = 0; im < 2; im++) {
                mma16(sacc[im][0], ah[im], bl4);
                mma16(sacc[im][0], al[im], bh4);
                mma16(sacc[im][0], ah[im], bh4);
                mma16(sacc[im][1], ah[im], bl4 + 2);
                mma16(sacc[im][1], al[im], bh4 + 2);
                mma16(sacc[im][1], ah[im], bh4 + 2);
            }
        }
#pragma unroll
        for (int im = 0; im < 2; im++) {
            int r0 = wm + im * 16 + (lane >> 2);
#pragma unroll
            for (int in = 0; in < 2; in++) {
                int c0 = cb * 128 + wk + in * 8 + ((lane & 3) << 1);
                Ssm[r0 * SSS + c0]           = __float_as_uint(sacc[im][in][0]);
                Ssm[r0 * SSS + c0 + 1]       = __float_as_uint(sacc[im][in][1]);
                Ssm[(r0 + 8) * SSS + c0]     = __float_as_uint(sacc[im][in][2]);
                Ssm[(r0 + 8) * SSS + c0 + 1] = __float_as_uint(sacc[im][in][3]);
            }
        }
        __syncthreads();
    }

    // ---- softmax (16 warps x 4 rows of 256); P stored as tf32 ----
#pragma unroll
    for (int rr = 0; rr < 4; rr++) {
        int row = warp * 4 + rr;
        float v[8];
        float mx = -3.0e38f;
#pragma unroll
        for (int i = 0; i < 8; i++) {
            v[i] = __uint_as_float(Ssm[row * SSS + lane + (i << 5)]);
            mx = fmaxf(mx, v[i]);
        }
#pragma unroll
        for (int off = 16; off; off >>= 1) mx = fmaxf(mx, __shfl_xor_sync(0xffffffffu, mx, off));
        float sum = 0.f;
#pragma unroll
        for (int i = 0; i < 8; i++) { v[i] = __expf(v[i] - mx); sum += v[i]; }
#pragma unroll
        for (int off = 16; off; off >>= 1) sum += __shfl_xor_sync(0xffffffffu, sum, off);
        float inv = 1.0f / sum;
#pragma unroll
        for (int i = 0; i < 8; i++) Ssm[row * SSS + lane + (i << 5)] = f2tf(v[i] * inv);
    }
    __syncthreads();

    // ---- O = P @ V (1x tf32): two 128-token chunks, ldmatrix B ----
    const int wc = (warp & 7) * 24;
    const int vrow = (lane & 7) + ((lane & 16) ? 8 : 0);
    const int vkw  = (lane & 8) ? 4 : 0;
    float oacc[2][3][4];
#pragma unroll
    for (int i = 0; i < 2; i++)
#pragma unroll
        for (int j = 0; j < 3; j++)
#pragma unroll
            for (int r = 0; r < 4; r++) oacc[i][j][r] = 0.f;

    const size_t vbase = (size_t)w * C_ * NTOK;
    for (int vb = 0; vb < 2; vb++) {
#pragma unroll
        for (int t = tid; t < 192 * 32; t += 512) {
            int ch = t >> 5, t4 = (t & 31) << 2;
            float4 v = *reinterpret_cast<const float4*>(
                g_v + vbase + (size_t)ch * NTOK + vb * 128 + t4);
            uint32_t* d = &Vs[ch * VS2 + t4];
            d[0] = f2tf(v.x); d[1] = f2tf(v.y); d[2] = f2tf(v.z); d[3] = f2tf(v.w);
        }
        __syncthreads();

#pragma unroll
        for (int kk = 0; kk < 128; kk += 8) {
            uint32_t a[2][4], b4[4], b2[2];
            int awrd = vb * 128 + kk + asel;
            ldsm4(a[0], sptr(&Ssm[arow * SSS + awrd]));
            ldsm4(a[1], sptr(&Ssm[(arow + 16) * SSS + awrd]));
            ldsm4(b4, sptr(&Vs[(wc + vrow) * VS2 + kk + vkw]));
            ldsm2(b2, sptr(&Vs[(wc + 16 + (lane & 7)) * VS2 + kk + vkw]));
#pragma unroll
            for (int im = 0; im < 2; im++) {
                mma8(oacc[im][0], a[im], b4);
                mma8(oacc[im][1], a[im], b4 + 2);
                mma8(oacc[im][2], a[im], b2);
            }
        }
        __syncthreads();
    }

    // ---- fused proj: write O (tf32) to Osm[tok][ch], fill Wsm, GEMM ----
#pragma unroll
    for (int im = 0; im < 2; im++) {
        int q0 = wm + im * 16 + (lane >> 2);   // token within qb block
#pragma unroll
        for (int in = 0; in < 3; in++) {
            int c0 = wc + in * 8 + ((lane & 3) << 1);
            Osm[q0 * OS2 + c0]           = f2tf(oacc[im][in][0]);
            Osm[q0 * OS2 + c0 + 1]       = f2tf(oacc[im][in][1]);
            Osm[(q0 + 8) * OS2 + c0]     = f2tf(oacc[im][in][2]);
            Osm[(q0 + 8) * OS2 + c0 + 1] = f2tf(oacc[im][in][3]);
        }
    }
    // Wsm: whole W_proj [192][192] as tf32 (stride 196)
#pragma unroll
    for (int t = tid; t < 192 * 48; t += 512) {
        int r = t / 48, c4 = (t % 48) << 2;
        float4 v = *reinterpret_cast<const float4*>(&proj_w[r * C_ + c4]);
        uint32_t* d = &Wsm[r * OS2 + c4];
        d[0] = f2tf(v.x); d[1] = f2tf(v.y); d[2] = f2tf(v.z); d[3] = f2tf(v.w);
    }
    __syncthreads();

    // GEMM: out[192 ch][64 tok] = W @ O^T. Warp grid 4m x 4n.
    const int wmp = (warp & 3) * 48;
    const int wnp = (warp >> 2) * 16;
    const int parow = (lane & 7) + ((lane & 8) ? 8 : 0);
    const int pasel = (lane & 16) ? 4 : 0;
    const int pbrow = (lane & 7) + ((lane & 16) ? 8 : 0);
    const int pbkw = (lane & 8) ? 4 : 0;

    float pacc[3][2][4];
#pragma unroll
    for (int i = 0; i < 3; i++)
#pragma unroll
        for (int j = 0; j < 2; j++)
#pragma unroll
            for (int r = 0; r < 4; r++) pacc[i][j][r] = 0.f;

#pragma unroll
    for (int kk = 0; kk < 192; kk += 8) {
        uint32_t a[3][4], b4[4];
#pragma unroll
        for (int i = 0; i < 3; i++)
            ldsm4(a[i], sptr(&Wsm[(wmp + i * 16 + parow) * OS2 + kk + pasel]));
        ldsm4(b4, sptr(&Osm[(wnp + pbrow) * OS2 + kk + pbkw]));
#pragma unroll
        for (int i = 0; i < 3; i++) {
            mma8(pacc[i][0], a[i], b4);
            mma8(pacc[i][1], a[i], b4 + 2);
        }
    }

    // epilogue: out = pacc + bias + x (residual)
#pragma unroll
    for (int i = 0; i < 3; i++) {
        int ch = wmp + i * 16 + (lane >> 2);
        float b0 = proj_b[ch];
        float b1 = proj_b[ch + 8];
#pragma unroll
        for (int j = 0; j < 2; j++) {
            int tok = qb * 64 + wnp + j * 8 + ((lane & 3) << 1);
            int ti = tok >> 4, tj = tok & 15;
            size_t g0 = (((size_t)b * C_ + ch) * 256 + wh * 16 + ti) * 256 + ww * 16 + tj;
            size_t g1 = (((size_t)b * C_ + ch + 8) * 256 + wh * 16 + ti) * 256 + ww * 16 + tj;
            float2 x0 = *reinterpret_cast<const float2*>(&x[g0]);
            float2 x1 = *reinterpret_cast<const float2*>(&x[g1]);
            float2 r0, r1;
            r0.x = pacc[i][j][0] + b0 + x0.x;
            r0.y = pacc[i][j][1] + b0 + x0.y;
            r1.x = pacc[i][j][2] + b1 + x1.x;
            r1.y = pacc[i][j][3] + b1 + x1.y;
            *reinterpret_cast<float2*>(&out[g0]) = r0;
            *reinterpret_cast<float2*>(&out[g1]) = r1;
        }
    }
}

// ---------------------------------------------------------------------------
namespace {
struct WarmUp {
    WarmUp() {
        void* p = nullptr;
        cudaGetSymbolAddress(&p, g_q);
        cudaGetSymbolAddress(&p, g_k);
        cudaGetSymbolAddress(&p, g_v);
        cudaGetSymbolAddress(&p, g_wqkh);
        cudaGetSymbolAddress(&p, g_wqkl);
        cudaFuncSetAttribute(attn_kernel, cudaFuncAttributeMaxDynamicSharedMemorySize,
                             (int)SMEM_ATTN_BYTES);
        cudaFuncSetAttribute(qkv_kernel, cudaFuncAttributeMaxDynamicSharedMemorySize,
                             (int)SMEM_QKV_BYTES);
    }
};
WarmUp warm_;
}  // namespace

extern "C" void kernel_launch(void* const* d_in, const int* in_sizes, int n_in,
                              void* d_out, int out_size) {
    (void)in_sizes; (void)n_in; (void)out_size;
    const float* x      = (const float*)d_in[0];
    const float* qkv_w  = (const float*)d_in[1];
    const float* qkv_b  = (const float*)d_in[2];
    const float* proj_w = (const float*)d_in[3];
    const float* proj_b = (const float*)d_in[4];
    float* out = (float*)d_out;

    cudaFuncSetAttribute(attn_kernel, cudaFuncAttributeMaxDynamicSharedMemorySize,
                         (int)SMEM_ATTN_BYTES);
    cudaFuncSetAttribute(qkv_kernel, cudaFuncAttributeMaxDynamicSharedMemorySize,
                         (int)SMEM_QKV_BYTES);

    split_w_kernel<<<144, 256>>>(qkv_w);
    qkv_kernel<<<dim3(9, NWIN), 256, SMEM_QKV_BYTES>>>(x, qkv_w, qkv_b);
    attn_kernel<<<dim3(4, NWIN), 512, SMEM_ATTN_BYTES>>>(x, proj_w, proj_b, out);
}

// round 11
// speedup vs baseline: 1.1371x; 1.0147x over previous
#include <cuda_runtime.h>
#include <cuda_bf16.h>
#include <cstdint>

// ---------------------------------------------------------------------------
// TransformerBlock: windowed attention, B=4 C=192 H=W=256, 16x16 windows.
//   K0 : split W_qk -> bf16 hi/lo packed planes
//   K1 : merged qkv, grid (9, 1024). q/k stored as packed bf16 hi/lo planes
//        [win][ch][tok/2]; v stored as tf32 bits [win][ch][tok].
//   K2 : attention + fused proj, grid (4, 1024), 512 thr. All smem fills are
//        pure copies; S-phase A/B frags via ldmatrix.trans on [ch][tok] data.
// ---------------------------------------------------------------------------

constexpr int C_     = 192;
constexpr int NTOK   = 256;
constexpr int NWIN   = 1024;
constexpr int IMG    = 256 * 256;

// q/k packed bf16x2 (token pairs) hi/lo planes, [win][ch][tok/2]
__device__ uint32_t g_qh[(size_t)NWIN * C_ * 128];
__device__ uint32_t g_ql[(size_t)NWIN * C_ * 128];
__device__ uint32_t g_kh[(size_t)NWIN * C_ * 128];
__device__ uint32_t g_kl[(size_t)NWIN * C_ * 128];
__device__ uint32_t g_v [(size_t)NWIN * C_ * NTOK];   // tf32 bits [win][ch][tok]
__device__ uint32_t g_wqkh[384 * 96];
__device__ uint32_t g_wqkl[384 * 96];

__device__ __forceinline__ uint32_t f2tf(float x) {
    uint32_t u;
    asm("cvt.rna.tf32.f32 %0, %1;" : "=r"(u) : "f"(x));
    return u;
}
__device__ __forceinline__ void splitbf2(float x0, float x1, uint32_t& hi, uint32_t& lo) {
    __nv_bfloat16 h0 = __float2bfloat16_rn(x0);
    __nv_bfloat16 h1 = __float2bfloat16_rn(x1);
    __nv_bfloat16 l0 = __float2bfloat16_rn(x0 - __bfloat162float(h0));
    __nv_bfloat16 l1 = __float2bfloat16_rn(x1 - __bfloat162float(h1));
    hi = ((uint32_t)__bfloat16_as_ushort(h1) << 16) | __bfloat16_as_ushort(h0);
    lo = ((uint32_t)__bfloat16_as_ushort(l1) << 16) | __bfloat16_as_ushort(l0);
}
__device__ __forceinline__ uint32_t sptr(const void* p) {
    return (uint32_t)__cvta_generic_to_shared(p);
}
__device__ __forceinline__ void ldsm4(uint32_t* r, uint32_t a) {
    asm volatile("ldmatrix.sync.aligned.m8n8.x4.shared.b16 {%0,%1,%2,%3}, [%4];"
        : "=r"(r[0]), "=r"(r[1]), "=r"(r[2]), "=r"(r[3]) : "r"(a));
}
__device__ __forceinline__ void ldsm2(uint32_t* r, uint32_t a) {
    asm volatile("ldmatrix.sync.aligned.m8n8.x2.shared.b16 {%0,%1}, [%2];"
        : "=r"(r[0]), "=r"(r[1]) : "r"(a));
}
__device__ __forceinline__ void ldsm4t(uint32_t* r, uint32_t a) {
    asm volatile("ldmatrix.sync.aligned.m8n8.x4.trans.shared.b16 {%0,%1,%2,%3}, [%4];"
        : "=r"(r[0]), "=r"(r[1]), "=r"(r[2]), "=r"(r[3]) : "r"(a));
}
__device__ __forceinline__ void mma8(float* d, const uint32_t* a, const uint32_t* b) {
    asm volatile(
        "mma.sync.aligned.m16n8k8.row.col.f32.tf32.tf32.f32 "
        "{%0,%1,%2,%3}, {%4,%5,%6,%7}, {%8,%9}, {%0,%1,%2,%3};\n"
        : "+f"(d[0]), "+f"(d[1]), "+f"(d[2]), "+f"(d[3])
        : "r"(a[0]), "r"(a[1]), "r"(a[2]), "r"(a[3]),
          "r"(b[0]), "r"(b[1]));
}
__device__ __forceinline__ void mma16(float* d, const uint32_t* a, const uint32_t* b) {
    asm volatile(
        "mma.sync.aligned.m16n8k16.row.col.f32.bf16.bf16.f32 "
        "{%0,%1,%2,%3}, {%4,%5,%6,%7}, {%8,%9}, {%0,%1,%2,%3};\n"
        : "+f"(d[0]), "+f"(d[1]), "+f"(d[2]), "+f"(d[3])
        : "r"(a[0]), "r"(a[1]), "r"(a[2]), "r"(a[3]),
          "r"(b[0]), "r"(b[1]));
}

// ===========================================================================
// K0: split W_qk rows [0,384) into bf16 hi/lo packed planes.
// ===========================================================================
__global__ void split_w_kernel(const float* __restrict__ qkv_w) {
    int idx = blockIdx.x * 256 + threadIdx.x;
    if (idx >= 384 * 96) return;
    int r = idx / 96, c = idx % 96;
    uint32_t h, l;
    splitbf2(qkv_w[r * C_ + 2 * c], qkv_w[r * C_ + 2 * c + 1], h, l);
    g_wqkh[idx] = h;
    g_wqkl[idx] = l;
}

// ===========================================================================
// K1: merged qkv. grid (9, 1024), 256 thr, 2 CTA/SM. smem 44032 B.
// ===========================================================================
constexpr int AS3 = 20;
constexpr int BT16 = 264;
constexpr size_t SMEM_QKV_BYTES = (size_t)(2 * 64 * AS3 + 2 * 32 * 132) * 4;  // 44032

__global__ void __launch_bounds__(256, 2) qkv_kernel(const float* __restrict__ x,
                                                     const float* __restrict__ qkv_w,
                                                     const float* __restrict__ qkv_b) {
    extern __shared__ uint32_t smq[];

    const int w  = blockIdx.y;
    const int b  = w >> 8, wh = (w >> 4) & 15, ww = w & 15;
    const int tid = threadIdx.x, warp = tid >> 5, lane = tid & 31;
    const int wm = (warp >> 2) << 5;
    const int wn = (warp & 3) << 6;
    const float* xw = x + (size_t)b * C_ * IMG + (size_t)(wh * 16) * 256 + ww * 16;

    float acc[2][8][4];
#pragma unroll
    for (int i = 0; i < 2; i++)
#pragma unroll
        for (int j = 0; j < 8; j++)
#pragma unroll
            for (int r = 0; r < 4; r++) acc[i][j][r] = 0.f;

    if (blockIdx.x < 6) {
        // ---------------- q/k path: 3x bf16 ----------------
        uint32_t* Ah = smq;
        uint32_t* Al = Ah + 64 * AS3;
        uint16_t* Bh16 = (uint16_t*)(smq + 2 * 64 * AS3);
        uint16_t* Bl16 = Bh16 + 32 * BT16;
        const int m0 = blockIdx.x * 64;

        const int arow = wm + (lane & 7) + ((lane & 8) ? 8 : 0);
        const int asel = (lane & 16) ? 4 : 0;
        const int brow0 = (lane & 7) + ((lane & 8) ? 8 : 0);
        const int bsel = (lane & 16) ? 8 : 0;

        for (int k0 = 0; k0 < C_; k0 += 32) {
            const int kw0 = k0 >> 1;
#pragma unroll
            for (int t = tid; t < 256; t += 256) {
                int r = t >> 2, c4 = (t & 3) << 2;
                *reinterpret_cast<uint4*>(&Ah[r * AS3 + c4]) =
                    *reinterpret_cast<const uint4*>(&g_wqkh[(m0 + r) * 96 + kw0 + c4]);
                *reinterpret_cast<uint4*>(&Al[r * AS3 + c4]) =
                    *reinterpret_cast<const uint4*>(&g_wqkl[(m0 + r) * 96 + kw0 + c4]);
            }
#pragma unroll
            for (int t = tid; t < 2048; t += 256) {
                int c = t >> 6, q = t & 63;
                int i = q >> 2, j4 = (q & 3) << 2;
                float4 v = *reinterpret_cast<const float4*>(
                    xw + (size_t)(k0 + c) * IMG + i * 256 + j4);
                int tok = i * 16 + j4;
                uint32_t h01, l01, h23, l23;
                splitbf2(v.x, v.y, h01, l01);
                splitbf2(v.z, v.w, h23, l23);
                uint32_t* dh = reinterpret_cast<uint32_t*>(&Bh16[c * BT16 + tok]);
                uint32_t* dl = reinterpret_cast<uint32_t*>(&Bl16[c * BT16 + tok]);
                dh[0] = h01; dh[1] = h23;
                dl[0] = l01; dl[1] = l23;
            }
            __syncthreads();

#pragma unroll
            for (int kk = 0; kk < 32; kk += 16) {
                uint32_t ah[2][4], al[2][4];
                int awrd = (kk >> 1) + asel;
                ldsm4(ah[0], sptr(&Ah[arow * AS3 + awrd]));
                ldsm4(ah[1], sptr(&Ah[(arow + 16) * AS3 + awrd]));
                ldsm4(al[0], sptr(&Al[arow * AS3 + awrd]));
                ldsm4(al[1], sptr(&Al[(arow + 16) * AS3 + awrd]));
                int brow = kk + brow0;
#pragma unroll
                for (int inp = 0; inp < 4; inp++) {
                    int n0 = wn + inp * 16 + bsel;
                    uint32_t bh4[4], bl4[4];
                    ldsm4t(bh4, sptr(&Bh16[brow * BT16 + n0]));
                    ldsm4t(bl4, sptr(&Bl16[brow * BT16 + n0]));
#pragma unroll
                    for (int im = 0; im < 2; im++) {
                        mma16(acc[im][2 * inp],     ah[im], bl4);
                        mma16(acc[im][2 * inp],     al[im], bh4);
                        mma16(acc[im][2 * inp],     ah[im], bh4);
                        mma16(acc[im][2 * inp + 1], ah[im], bl4 + 2);
                        mma16(acc[im][2 * inp + 1], al[im], bh4 + 2);
                        mma16(acc[im][2 * inp + 1], ah[im], bh4 + 2);
                    }
                }
            }
            __syncthreads();
        }

        // epilogue: +bias, split to packed bf16 hi/lo planes [ch][tok/2]
        const int sec = m0 / 192;
        const int ob  = m0 % 192;
        uint32_t* dh = (sec == 0) ? g_qh : g_kh;
        uint32_t* dl = (sec == 0) ? g_ql : g_kl;
        const size_t base = (size_t)w * C_ * 128;
#pragma unroll
        for (int im = 0; im < 2; im++) {
            int mr = wm + im * 16 + (lane >> 2);
            float b0 = qkv_b[m0 + mr];
            float b1 = qkv_b[m0 + mr + 8];
#pragma unroll
            for (int in = 0; in < 8; in++) {
                int n0 = wn + in * 8 + ((lane & 3) << 1);
                int wi = n0 >> 1;
                uint32_t h, l;
                splitbf2(acc[im][in][0] + b0, acc[im][in][1] + b0, h, l);
                dh[base + (size_t)(ob + mr) * 128 + wi] = h;
                dl[base + (size_t)(ob + mr) * 128 + wi] = l;
                splitbf2(acc[im][in][2] + b1, acc[im][in][3] + b1, h, l);
                dh[base + (size_t)(ob + mr + 8) * 128 + wi] = h;
                dl[base + (size_t)(ob + mr + 8) * 128 + wi] = l;
            }
        }
    } else {
        // ---------------- v path: 1x tf32, output tf32 bits [ch][tok] ------
        uint32_t* As = smq;
        uint32_t* Bs = As + 64 * 36;
        const int m0 = 384 + (blockIdx.x - 6) * 64;

        const int arow = wm + (lane & 7) + ((lane & 8) ? 8 : 0);
        const int asel = (lane & 16) ? 4 : 0;

        for (int k0 = 0; k0 < C_; k0 += 32) {
#pragma unroll
            for (int t = tid; t < 512; t += 256) {
                int r = t >> 3, c4 = (t & 7) << 2;
                float4 v = *reinterpret_cast<const float4*>(&qkv_w[(m0 + r) * C_ + k0 + c4]);
                uint4 h;
                h.x = f2tf(v.x); h.y = f2tf(v.y); h.z = f2tf(v.z); h.w = f2tf(v.w);
                *reinterpret_cast<uint4*>(&As[r * 36 + c4]) = h;
            }
#pragma unroll
            for (int t = tid; t < 2048; t += 256) {
                int c = t >> 6, q = t & 63;
                int i = q >> 2, j4 = (q & 3) << 2;
                float4 v = *reinterpret_cast<const float4*>(
                    xw + (size_t)(k0 + c) * IMG + i * 256 + j4);
                uint4 h;
                h.x = f2tf(v.x); h.y = f2tf(v.y); h.z = f2tf(v.z); h.w = f2tf(v.w);
                *reinterpret_cast<uint4*>(&Bs[c * 264 + i * 16 + j4]) = h;
            }
            __syncthreads();

#pragma unroll
            for (int kk = 0; kk < 32; kk += 8) {
                uint32_t a[2][4];
                int awrd = kk + asel;
                ldsm4(a[0], sptr(&As[arow * 36 + awrd]));
                ldsm4(a[1], sptr(&As[(arow + 16) * 36 + awrd]));
#pragma unroll
                for (int in = 0; in < 8; in++) {
                    int col = wn + in * 8 + (lane >> 2);
                    uint32_t bf[2];
                    bf[0] = Bs[(kk + (lane & 3)) * 264 + col];
                    bf[1] = Bs[(kk + 4 + (lane & 3)) * 264 + col];
#pragma unroll
                    for (int im = 0; im < 2; im++) mma8(acc[im][in], a[im], bf);
                }
            }
            __syncthreads();
        }

        const int ob = m0 - 384;
        const size_t base = (size_t)w * C_ * NTOK;
#pragma unroll
        for (int im = 0; im < 2; im++) {
            int mr = wm + im * 16 + (lane >> 2);
            float b0 = qkv_b[m0 + mr];
            float b1 = qkv_b[m0 + mr + 8];
#pragma unroll
            for (int in = 0; in < 8; in++) {
                int n0 = wn + in * 8 + ((lane & 3) << 1);
                uint2 r0, r1;
                r0.x = f2tf(acc[im][in][0] + b0); r0.y = f2tf(acc[im][in][1] + b0);
                r1.x = f2tf(acc[im][in][2] + b1); r1.y = f2tf(acc[im][in][3] + b1);
                *reinterpret_cast<uint2*>(&g_v[base + (size_t)(ob + mr) * NTOK + n0])     = r0;
                *reinterpret_cast<uint2*>(&g_v[base + (size_t)(ob + mr + 8) * NTOK + n0]) = r1;
            }
        }
    }
}

// ===========================================================================
// K2: attention + fused proj. grid (4, 1024), 512 thr. smem 226304 B.
// Regions (words): Qh16[0,6912) Ql16[6912,13824) Kh16[13824,26880)
//                  Kl16[26880,39936) Ssm[39936,56576)
// Q planes [192 ch][72 b16] (64 tok + pad), K planes [192][136 b16].
// V phase: Vs = word 13824 as [192][132]. Proj: Osm at 0, Wsm at 13824.
// ===========================================================================
constexpr int QST = 72;     // Q smem stride in b16
constexpr int KST = 136;    // K smem stride in b16
constexpr int VS2 = 132;
constexpr int SSS = 260;
constexpr int OS2 = 196;
constexpr size_t SMEM_ATTN_BYTES = 56576u * 4;   // 226304

__global__ void __launch_bounds__(512, 1) attn_kernel(const float* __restrict__ x,
                                                      const float* __restrict__ proj_w,
                                                      const float* __restrict__ proj_b,
                                                      float* __restrict__ out) {
    extern __shared__ uint32_t sm[];
    uint16_t* Qh16 = (uint16_t*)sm;
    uint16_t* Ql16 = (uint16_t*)(sm + 6912);
    uint16_t* Kh16 = (uint16_t*)(sm + 13824);
    uint16_t* Kl16 = (uint16_t*)(sm + 26880);
    uint32_t* Ssm  = sm + 39936;
    uint32_t* Vs   = sm + 13824;        // [192][132] during PV
    uint32_t* Osm  = sm;                // [64][196] proj phase
    uint32_t* Wsm  = sm + 13824;        // [192][196] proj phase

    const int qb = blockIdx.x, w = blockIdx.y;
    const int b  = w >> 8, wh = (w >> 4) & 15, ww = w & 15;
    const int tid = threadIdx.x, warp = tid >> 5, lane = tid & 31;

    // Q fill: pure copy of packed planes, rows=ch, 32 words (64 tok)
    {
        const uint32_t* qh = g_qh + (size_t)w * C_ * 128 + qb * 32;
        const uint32_t* ql = g_ql + (size_t)w * C_ * 128 + qb * 32;
        uint32_t* Qhw = (uint32_t*)Qh16;
        uint32_t* Qlw = (uint32_t*)Ql16;
#pragma unroll
        for (int t = tid; t < 192 * 8; t += 512) {
            int r = t >> 3, g4 = (t & 7) << 2;
            *reinterpret_cast<uint4*>(&Qhw[r * 36 + g4]) =
                *reinterpret_cast<const uint4*>(&qh[(size_t)r * 128 + g4]);
            *reinterpret_cast<uint4*>(&Qlw[r * 36 + g4]) =
                *reinterpret_cast<const uint4*>(&ql[(size_t)r * 128 + g4]);
        }
    }

    const int wm = (warp >> 3) << 5;    // tok group 0/32
    const int wk = (warp & 7) << 4;     // key group (16 keys)
    // A (Q, trans): rows = ch, cols = tok
    const int qk_r = (lane & 7) + ((lane & 16) ? 8 : 0);
    const int qtok = (lane & 8) ? 8 : 0;
    // B (K, trans): rows = ch, cols = key
    const int kk_r = (lane & 7) + ((lane & 8) ? 8 : 0);
    const int ksel = (lane & 16) ? 8 : 0;

    // ---- S = Q K^T (3x bf16): two 128-key chunks ----
    for (int cb = 0; cb < 2; cb++) {
        {
            const uint32_t* kh = g_kh + (size_t)w * C_ * 128 + cb * 64;
            const uint32_t* kl = g_kl + (size_t)w * C_ * 128 + cb * 64;
            uint32_t* Khw = (uint32_t*)Kh16;
            uint32_t* Klw = (uint32_t*)Kl16;
#pragma unroll
            for (int t = tid; t < 192 * 16; t += 512) {
                int r = t >> 4, g4 = (t & 15) << 2;
                *reinterpret_cast<uint4*>(&Khw[r * 68 + g4]) =
                    *reinterpret_cast<const uint4*>(&kh[(size_t)r * 128 + g4]);
                *reinterpret_cast<uint4*>(&Klw[r * 68 + g4]) =
                    *reinterpret_cast<const uint4*>(&kl[(size_t)r * 128 + g4]);
            }
        }
        __syncthreads();

        float sacc[2][2][4];
#pragma unroll
        for (int i = 0; i < 2; i++)
#pragma unroll
            for (int j = 0; j < 2; j++)
#pragma unroll
                for (int r = 0; r < 4; r++) sacc[i][j][r] = 0.f;

#pragma unroll
        for (int kk2 = 0; kk2 < 192; kk2 += 16) {
            uint32_t ah[2][4], al[2][4], bh4[4], bl4[4];
#pragma unroll
            for (int im = 0; im < 2; im++) {
                int col = wm + im * 16 + qtok;
                ldsm4t(ah[im], sptr(&Qh16[(kk2 + qk_r) * QST + col]));
                ldsm4t(al[im], sptr(&Ql16[(kk2 + qk_r) * QST + col]));
            }
            ldsm4t(bh4, sptr(&Kh16[(kk2 + kk_r) * KST + wk + ksel]));
            ldsm4t(bl4, sptr(&Kl16[(kk2 + kk_r) * KST + wk + ksel]));
#pragma unroll
            for (int im = 0; im < 2; im++) {
                mma16(sacc[im][0], ah[im], bl4);
                mma16(sacc[im][0], al[im], bh4);
                mma16(sacc[im][0], ah[im], bh4);
                mma16(sacc[im][1], ah[im], bl4 + 2);
                mma16(sacc[im][1], al[im], bh4 + 2);
                mma16(sacc[im][1], ah[im], bh4 + 2);
            }
        }
#pragma unroll
        for (int im = 0; im < 2; im++) {
            int r0 = wm + im * 16 + (lane >> 2);
#pragma unroll
            for (int in = 0; in < 2; in++) {
                int c0 = cb * 128 + wk + in * 8 + ((lane & 3) << 1);
                Ssm[r0 * SSS + c0]           = __float_as_uint(sacc[im][in][0]);
                Ssm[r0 * SSS + c0 + 1]       = __float_as_uint(sacc[im][in][1]);
                Ssm[(r0 + 8) * SSS + c0]     = __float_as_uint(sacc[im][in][2]);
                Ssm[(r0 + 8) * SSS + c0 + 1] = __float_as_uint(sacc[im][in][3]);
            }
        }
        __syncthreads();
    }

    // ---- softmax (16 warps x 4 rows of 256); P stored as tf32 ----
#pragma unroll
    for (int rr = 0; rr < 4; rr++) {
        int row = warp * 4 + rr;
        float v[8];
        float mx = -3.0e38f;
#pragma unroll
        for (int i = 0; i < 8; i++) {
            v[i] = __uint_as_float(Ssm[row * SSS + lane + (i << 5)]);
            mx = fmaxf(mx, v[i]);
        }
#pragma unroll
        for (int off = 16; off; off >>= 1) mx = fmaxf(mx, __shfl_xor_sync(0xffffffffu, mx, off));
        float sum = 0.f;
#pragma unroll
        for (int i = 0; i < 8; i++) { v[i] = __expf(v[i] - mx); sum += v[i]; }
#pragma unroll
        for (int off = 16; off; off >>= 1) sum += __shfl_xor_sync(0xffffffffu, sum, off);
        float inv = 1.0f / sum;
#pragma unroll
        for (int i = 0; i < 8; i++) Ssm[row * SSS + lane + (i << 5)] = f2tf(v[i] * inv);
    }
    __syncthreads();

    // ---- O = P @ V (1x tf32): two 128-token chunks; V copy (tf32 bits) ----
    const int wc = (warp & 7) * 24;
    const int arow = wm + (lane & 7) + ((lane & 8) ? 8 : 0);
    const int asel = (lane & 16) ? 4 : 0;
    const int vrow = (lane & 7) + ((lane & 16) ? 8 : 0);
    const int vkw  = (lane & 8) ? 4 : 0;
    float oacc[2][3][4];
#pragma unroll
    for (int i = 0; i < 2; i++)
#pragma unroll
        for (int j = 0; j < 3; j++)
#pragma unroll
            for (int r = 0; r < 4; r++) oacc[i][j][r] = 0.f;

    const size_t vbase = (size_t)w * C_ * NTOK;
    for (int vb = 0; vb < 2; vb++) {
#pragma unroll
        for (int t = tid; t < 192 * 32; t += 512) {
            int ch = t >> 5, t4 = (t & 31) << 2;
            *reinterpret_cast<uint4*>(&Vs[ch * VS2 + t4]) =
                *reinterpret_cast<const uint4*>(&g_v[vbase + (size_t)ch * NTOK + vb * 128 + t4]);
        }
        __syncthreads();

#pragma unroll
        for (int kk = 0; kk < 128; kk += 8) {
            uint32_t a[2][4], b4[4], b2[2];
            int awrd = vb * 128 + kk + asel;
            ldsm4(a[0], sptr(&Ssm[arow * SSS + awrd]));
            ldsm4(a[1], sptr(&Ssm[(arow + 16) * SSS + awrd]));
            ldsm4(b4, sptr(&Vs[(wc + vrow) * VS2 + kk + vkw]));
            ldsm2(b2, sptr(&Vs[(wc + 16 + (lane & 7)) * VS2 + kk + vkw]));
#pragma unroll
            for (int im = 0; im < 2; im++) {
                mma8(oacc[im][0], a[im], b4);
                mma8(oacc[im][1], a[im], b4 + 2);
                mma8(oacc[im][2], a[im], b2);
            }
        }
        __syncthreads();
    }

    // ---- fused proj: O (tf32) -> Osm[tok][ch], fill Wsm, GEMM ----
#pragma unroll
    for (int im = 0; im < 2; im++) {
        int q0 = wm + im * 16 + (lane >> 2);
#pragma unroll
        for (int in = 0; in < 3; in++) {
            int c0 = wc + in * 8 + ((lane & 3) << 1);
            Osm[q0 * OS2 + c0]           = f2tf(oacc[im][in][0]);
            Osm[q0 * OS2 + c0 + 1]       = f2tf(oacc[im][in][1]);
            Osm[(q0 + 8) * OS2 + c0]     = f2tf(oacc[im][in][2]);
            Osm[(q0 + 8) * OS2 + c0 + 1] = f2tf(oacc[im][in][3]);
        }
    }
#pragma unroll
    for (int t = tid; t < 192 * 48; t += 512) {
        int r = t / 48, c4 = (t % 48) << 2;
        float4 v = *reinterpret_cast<const float4*>(&proj_w[r * C_ + c4]);
        uint32_t* d = &Wsm[r * OS2 + c4];
        d[0] = f2tf(v.x); d[1] = f2tf(v.y); d[2] = f2tf(v.z); d[3] = f2tf(v.w);
    }
    __syncthreads();

    const int wmp = (warp & 3) * 48;
    const int wnp = (warp >> 2) * 16;
    const int parow = (lane & 7) + ((lane & 8) ? 8 : 0);
    const int pasel = (lane & 16) ? 4 : 0;
    const int pbrow = (lane & 7) + ((lane & 16) ? 8 : 0);
    const int pbkw = (lane & 8) ? 4 : 0;

    float pacc[3][2][4];
#pragma unroll
    for (int i = 0; i < 3; i++)
#pragma unroll
        for (int j = 0; j < 2; j++)
#pragma unroll
            for (int r = 0; r < 4; r++) pacc[i][j][r] = 0.f;

#pragma unroll
    for (int kk = 0; kk < 192; kk += 8) {
        uint32_t a[3][4], b4[4];
#pragma unroll
        for (int i = 0; i < 3; i++)
            ldsm4(a[i], sptr(&Wsm[(wmp + i * 16 + parow) * OS2 + kk + pasel]));
        ldsm4(b4, sptr(&Osm[(wnp + pbrow) * OS2 + kk + pbkw]));
#pragma unroll
        for (int i = 0; i < 3; i++) {
            mma8(pacc[i][0], a[i], b4);
            mma8(pacc[i][1], a[i], b4 + 2);
        }
    }

    // epilogue: out = pacc + bias + x (residual)
#pragma unroll
    for (int i = 0; i < 3; i++) {
        int ch = wmp + i * 16 + (lane >> 2);
        float b0 = proj_b[ch];
        float b1 = proj_b[ch + 8];
#pragma unroll
        for (int j = 0; j < 2; j++) {
            int tok = qb * 64 + wnp + j * 8 + ((lane & 3) << 1);
            int ti = tok >> 4, tj = tok & 15;
            size_t g0 = (((size_t)b * C_ + ch) * 256 + wh * 16 + ti) * 256 + ww * 16 + tj;
            size_t g1 = (((size_t)b * C_ + ch + 8) * 256 + wh * 16 + ti) * 256 + ww * 16 + tj;
            float2 x0 = *reinterpret_cast<const float2*>(&x[g0]);
            float2 x1 = *reinterpret_cast<const float2*>(&x[g1]);
            float2 r0, r1;
            r0.x = pacc[i][j][0] + b0 + x0.x;
            r0.y = pacc[i][j][1] + b0 + x0.y;
            r1.x = pacc[i][j][2] + b1 + x1.x;
            r1.y = pacc[i][j][3] + b1 + x1.y;
            *reinterpret_cast<float2*>(&out[g0]) = r0;
            *reinterpret_cast<float2*>(&out[g1]) = r1;
        }
    }
}

// ---------------------------------------------------------------------------
namespace {
struct WarmUp {
    WarmUp() {
        void* p = nullptr;
        cudaGetSymbolAddress(&p, g_qh);
        cudaGetSymbolAddress(&p, g_ql);
        cudaGetSymbolAddress(&p, g_kh);
        cudaGetSymbolAddress(&p, g_kl);
        cudaGetSymbolAddress(&p, g_v);
        cudaGetSymbolAddress(&p, g_wqkh);
        cudaGetSymbolAddress(&p, g_wqkl);
        cudaFuncSetAttribute(attn_kernel, cudaFuncAttributeMaxDynamicSharedMemorySize,
                             (int)SMEM_ATTN_BYTES);
        cudaFuncSetAttribute(qkv_kernel, cudaFuncAttributeMaxDynamicSharedMemorySize,
                             (int)SMEM_QKV_BYTES);
    }
};
WarmUp warm_;
}  // namespace

extern "C" void kernel_launch(void* const* d_in, const int* in_sizes, int n_in,
                              void* d_out, int out_size) {
    (void)in_sizes; (void)n_in; (void)out_size;
    const float* x      = (const float*)d_in[0];
    const float* qkv_w  = (const float*)d_in[1];
    const float* qkv_b  = (const float*)d_in[2];
    const float* proj_w = (const float*)d_in[3];
    const float* proj_b = (const float*)d_in[4];
    float* out = (float*)d_out;

    cudaFuncSetAttribute(attn_kernel, cudaFuncAttributeMaxDynamicSharedMemorySize,
                         (int)SMEM_ATTN_BYTES);
    cudaFuncSetAttribute(qkv_kernel, cudaFuncAttributeMaxDynamicSharedMemorySize,
                         (int)SMEM_QKV_BYTES);

    split_w_kernel<<<144, 256>>>(qkv_w);
    qkv_kernel<<<dim3(9, NWIN), 256, SMEM_QKV_BYTES>>>(x, qkv_w, qkv_b);
    attn_kernel<<<dim3(4, NWIN), 512, SMEM_ATTN_BYTES>>>(x, proj_w, proj_b, out);
}